// round 6
// baseline (speedup 1.0000x reference)
#include <cuda_runtime.h>
#include <cuda_fp16.h>
#include <math.h>
#include <stdint.h>

// Problem constants (fixed by the dataset)
#define TT 5
#define FIN 10
#define HID 16
#define MAXN 100000
#define MAXE 3200000
#define XSTRIDE 52        // padded T*FIN in halves (50 -> 52; pad stays zero)
#define XREAL  50
#define FSTRIDE 80        // T*HID

#define KB_BLOCKS 592     // resident-grid kernel: 4 blocks/SM * 148 SMs

// ---------------- device scratch (static: no allocation allowed) ----------------
__device__ int    g_cnt[MAXN];         // zero at load; re-zeroed each call
__device__ int    g_deg[MAXN];
__device__ int    g_row[MAXN];
__device__ int    g_cursor[MAXN];
__device__ int    g_total;
__device__ int    g_bar_count;         // grid barrier (returns to 0 after each use)
__device__ int    g_bar_phase;         // monotonic sense counter
__device__ float  g_dis[MAXN];
__device__ float  g_dinv[MAXN];
__device__ __align__(16) int2   g_edge[MAXE];   // .x = src, .y = half2(w,w) bits
__device__ __align__(16) __half g_xT[(size_t)MAXN * XSTRIDE];
__device__ __align__(16) __half g_h1[(size_t)MAXN * FSTRIDE];
__device__ __align__(16) __half g_feats[(size_t)MAXN * FSTRIDE];
__device__ __align__(16) __half g_P[(size_t)MAXN * FSTRIDE];
__device__ float  g_Mz[256], g_Mr[256], g_Mh[256];
__device__ float  g_Bz[16],  g_Br[16],  g_Bh[16];

__device__ __forceinline__ __half2 bits_h2(int b) {
    return *reinterpret_cast<__half2*>(&b);
}
__device__ __forceinline__ __half2 bits_h2u(unsigned b) {
    return *reinterpret_cast<__half2*>(&b);
}
__device__ __forceinline__ float fast_tanh(float x) {
    float r;
    asm("tanh.approx.f32 %0, %1;" : "=f"(r) : "f"(x));
    return r;
}
__device__ __forceinline__ float fast_sig(float x) {
    return fmaf(0.5f, fast_tanh(0.5f * x), 0.5f);
}

// ---------------- stage 0: fused degree count + x transpose (fp16) --------------
__global__ void kprep0(const int* __restrict__ dst, int* cnt,
                       const float* __restrict__ x, __half* __restrict__ xT,
                       int n, int e) {
    int i = blockIdx.x * blockDim.x + threadIdx.x;
    if (i == 0) g_total = 0;
    if (i < e) atomicAdd(&cnt[dst[i]], 1);
    if (i < n * XREAL) {
        int node = i / XREAL;
        int c = i - node * XREAL;
        int t = c / FIN;
        int f = c - t * FIN;
        xT[(size_t)node * XSTRIDE + c] =
            __float2half(x[((size_t)t * n + node) * FIN + f]);
    }
}

// ---------------- merged offsets + fill: resident grid + software barrier -------
__device__ __forceinline__ void grid_barrier(int nblocks) {
    __threadfence();
    __syncthreads();
    if (threadIdx.x == 0) {
        int p0 = atomicAdd(&g_bar_phase, 0);
        int t = atomicAdd(&g_bar_count, 1);
        if (t == nblocks - 1) {
            atomicExch(&g_bar_count, 0);
            __threadfence();
            atomicAdd(&g_bar_phase, 1);
        } else {
            while (atomicAdd(&g_bar_phase, 0) == p0) __nanosleep(64);
        }
    }
    __syncthreads();
    __threadfence();
}

__global__ __launch_bounds__(256, 4) void kbuild(const int* __restrict__ src,
                                                 const int* __restrict__ dst,
                                                 int* cnt, int2* edge, int n, int e) {
    __shared__ int sh[256];
    __shared__ int sbase;
    int tid = threadIdx.x;
    // Phase A: per-chunk scan -> node offsets, norms; reset cnt
    int nchunks = (n + 255) / 256;
    for (int chunk = blockIdx.x; chunk < nchunks; chunk += gridDim.x) {
        int i = chunk * 256 + tid;
        int deg = (i < n) ? cnt[i] : 0;
        sh[tid] = deg;
        __syncthreads();
        for (int off = 1; off < 256; off <<= 1) {
            int t = (tid >= off) ? sh[tid - off] : 0;
            __syncthreads();
            sh[tid] += t;
            __syncthreads();
        }
        if (tid == 255) sbase = atomicAdd(&g_total, sh[255]);
        __syncthreads();
        int start = sbase + sh[tid] - deg;
        if (i < n) {
            g_row[i]    = start;
            g_cursor[i] = start;
            g_deg[i]    = deg;
            cnt[i]      = 0;
            float d = (float)deg + 1.0f;
            g_dis[i]  = rsqrtf(d);
            g_dinv[i] = 1.0f / d;
        }
        __syncthreads();
    }
    // all offsets visible before fill
    grid_barrier(gridDim.x);
    // Phase B: fill edge list (unordered within each node's slice)
    int stride = gridDim.x * 256;
    for (int i = blockIdx.x * 256 + tid; i < e; i += stride) {
        int s = src[i], d = dst[i];
        int pos = atomicAdd(&g_cursor[d], 1);
        __half2 h2 = __float2half2_rn(g_dis[s] * g_dis[d]);
        edge[pos] = make_int2(s, *reinterpret_cast<int*>(&h2));
    }
}

// ---------------- propagation, hfma2 accumulate, no shfl ------------------------
// warp per destination node. Lane ll (clamped to NLOAD-1) owns 4 halves
// [4*ll, 4*ll+4) of the row, loaded as one uint2. All lanes walk the edge
// list with uniform int4-pair loads. 4 independent hfma2 chains.
// MODE 1: out(half) = relu((S in) @ W + b) per time slice (stride FSTRIDE).
// MODE 0: out(half) = S in (stride FSTRIDE).
template <int STRIDE_H, int NLOAD, int FIN_IN, int MODE>
__global__ __launch_bounds__(256) void kprop(const __half* __restrict__ in,
                                             __half* __restrict__ out,
                                             const int* __restrict__ rowp,
                                             const int* __restrict__ degv,
                                             const int2* __restrict__ edge,
                                             const float* __restrict__ dinv,
                                             const float* __restrict__ Wm,
                                             const float* __restrict__ bm, int n) {
    __shared__ float sAgg[MODE ? 8 : 1][MODE ? NLOAD * 4 : 4];
    __shared__ float sW[MODE ? FIN_IN * 16 : 1];
    __shared__ float sB[MODE ? 16 : 1];
    if (MODE) {
        for (int i = threadIdx.x; i < FIN_IN * 16; i += blockDim.x) sW[i] = Wm[i];
        if (threadIdx.x < 16) sB[threadIdx.x] = bm[threadIdx.x];
        __syncthreads();
    }
    int wwid = threadIdx.x >> 5;
    int node = (blockIdx.x << 3) + wwid;
    if (node >= n) return;
    int lane = threadIdx.x & 31;
    int ll = (lane < NLOAD) ? lane : (NLOAD - 1);   // clamp; extras discarded
    bool act = lane < NLOAD;

    __half2 zero2 = __float2half2_rn(0.f);
    __half2 a0x = zero2, a0y = zero2, a1x = zero2, a1y = zero2;
    __half2 a2x = zero2, a2y = zero2, a3x = zero2, a3y = zero2;

    int j = rowp[node];
    int end = j + degv[node];

    // peel to even j so int4 loads are 16B-aligned
    if ((j & 1) && j < end) {
        int2 e0 = __ldg(edge + j);
        uint2 q0 = __ldg((const uint2*)(in + (size_t)e0.x * STRIDE_H) + ll);
        __half2 w0 = bits_h2(e0.y);
        a0x = __hfma2(w0, bits_h2u(q0.x), a0x);
        a0y = __hfma2(w0, bits_h2u(q0.y), a0y);
        j++;
    }
    for (; j + 4 <= end; j += 4) {
        const int4* ep = (const int4*)(edge + j);
        int4 ea = __ldg(ep);
        int4 eb = __ldg(ep + 1);
        uint2 q0 = __ldg((const uint2*)(in + (size_t)ea.x * STRIDE_H) + ll);
        uint2 q1 = __ldg((const uint2*)(in + (size_t)ea.z * STRIDE_H) + ll);
        uint2 q2 = __ldg((const uint2*)(in + (size_t)eb.x * STRIDE_H) + ll);
        uint2 q3 = __ldg((const uint2*)(in + (size_t)eb.z * STRIDE_H) + ll);
        __half2 w0 = bits_h2(ea.y), w1 = bits_h2(ea.w);
        __half2 w2 = bits_h2(eb.y), w3 = bits_h2(eb.w);
        a0x = __hfma2(w0, bits_h2u(q0.x), a0x);
        a0y = __hfma2(w0, bits_h2u(q0.y), a0y);
        a1x = __hfma2(w1, bits_h2u(q1.x), a1x);
        a1y = __hfma2(w1, bits_h2u(q1.y), a1y);
        a2x = __hfma2(w2, bits_h2u(q2.x), a2x);
        a2y = __hfma2(w2, bits_h2u(q2.y), a2y);
        a3x = __hfma2(w3, bits_h2u(q3.x), a3x);
        a3y = __hfma2(w3, bits_h2u(q3.y), a3y);
    }
    for (; j < end; j++) {
        int2 e0 = __ldg(edge + j);
        uint2 q0 = __ldg((const uint2*)(in + (size_t)e0.x * STRIDE_H) + ll);
        __half2 w0 = bits_h2(e0.y);
        a0x = __hfma2(w0, bits_h2u(q0.x), a0x);
        a0y = __hfma2(w0, bits_h2u(q0.y), a0y);
    }

    // merge chains in fp32 + fp32 self-loop
    float di = dinv[node];
    uint2 sq = __ldg((const uint2*)(in + (size_t)node * STRIDE_H) + ll);
    float2 s01 = __half22float2(bits_h2u(sq.x));
    float2 s23 = __half22float2(bits_h2u(sq.y));
    float2 c0, c1, c2, c3;
    c0 = __half22float2(a0x); c1 = __half22float2(a1x);
    c2 = __half22float2(a2x); c3 = __half22float2(a3x);
    float f0 = (c0.x + c1.x) + (c2.x + c3.x) + di * s01.x;
    float f1 = (c0.y + c1.y) + (c2.y + c3.y) + di * s01.y;
    c0 = __half22float2(a0y); c1 = __half22float2(a1y);
    c2 = __half22float2(a2y); c3 = __half22float2(a3y);
    float f2 = (c0.x + c1.x) + (c2.x + c3.x) + di * s23.x;
    float f3 = (c0.y + c1.y) + (c2.y + c3.y) + di * s23.y;

    if (!MODE) {
        if (act) {
            __half2 o01 = __floats2half2_rn(f0, f1);
            __half2 o23 = __floats2half2_rn(f2, f3);
            uint2 pk;
            pk.x = *reinterpret_cast<unsigned*>(&o01);
            pk.y = *reinterpret_cast<unsigned*>(&o23);
            *((uint2*)(out + (size_t)node * FSTRIDE) + lane) = pk;
        }
        return;
    }

    // stage the aggregate, then per-slice dense transform + relu + fp16 pack
    if (act) {
        float4 fv = make_float4(f0, f1, f2, f3);
        *(float4*)&sAgg[wwid][lane * 4] = fv;
    }
    __syncwarp();
    if (lane < 20) {
        int c = lane * 4;         // 20 lanes x 4 outputs = 80
        int t = c >> 4;
        int h = c & 15;
        float o0 = sB[h], o1 = sB[h + 1], o2 = sB[h + 2], o3 = sB[h + 3];
#pragma unroll
        for (int f = 0; f < FIN_IN; f++) {
            float a = sAgg[wwid][t * FIN_IN + f];
            o0 = fmaf(a, sW[f * 16 + h],     o0);
            o1 = fmaf(a, sW[f * 16 + h + 1], o1);
            o2 = fmaf(a, sW[f * 16 + h + 2], o2);
            o3 = fmaf(a, sW[f * 16 + h + 3], o3);
        }
        __half2 p01 = __floats2half2_rn(fmaxf(o0, 0.f), fmaxf(o1, 0.f));
        __half2 p23 = __floats2half2_rn(fmaxf(o2, 0.f), fmaxf(o3, 0.f));
        uint2 pk;
        pk.x = *reinterpret_cast<unsigned*>(&p01);
        pk.y = *reinterpret_cast<unsigned*>(&p23);
        *((uint2*)(out + (size_t)node * FSTRIDE) + lane) = pk;
    }
}

// ---------------- fold gate matmuls: M* = W* @ L*[0:16], B* = b*@L*[0:16] + l* ----
__global__ void kprepG(const float* Wz, const float* bz, const float* Wr, const float* br,
                       const float* Wh, const float* bh,
                       const float* Lz, const float* lz, const float* Lr, const float* lr,
                       const float* Lh, const float* lh) {
    int tid = threadIdx.x;  // 256
    int k = tid >> 4, h = tid & 15;
    float mz = 0.f, mr = 0.f, mh = 0.f;
#pragma unroll
    for (int j = 0; j < 16; j++) {
        mz = fmaf(Wz[k * 16 + j], Lz[j * 16 + h], mz);
        mr = fmaf(Wr[k * 16 + j], Lr[j * 16 + h], mr);
        mh = fmaf(Wh[k * 16 + j], Lh[j * 16 + h], mh);
    }
    g_Mz[tid] = mz; g_Mr[tid] = mr; g_Mh[tid] = mh;
    if (tid < 16) {
        float az = lz[tid], ar = lr[tid], ah = lh[tid];
#pragma unroll
        for (int j = 0; j < 16; j++) {
            az = fmaf(bz[j], Lz[j * 16 + tid], az);
            ar = fmaf(br[j], Lr[j * 16 + tid], ar);
            ah = fmaf(bh[j], Lh[j * 16 + tid], ah);
        }
        g_Bz[tid] = az; g_Br[tid] = ar; g_Bh[tid] = ah;
    }
}

// ---------------- GRU + attention pooling + FC + log_softmax ---------------------
#define GRU_NPB 96
__global__ __launch_bounds__(GRU_NPB) void kgru(const __half* __restrict__ P,
                                                const float* __restrict__ Lz,
                                                const float* __restrict__ Lr,
                                                const float* __restrict__ Lh,
                                                const float* __restrict__ att,
                                                const float* __restrict__ fcW,
                                                const float* __restrict__ fcb,
                                                float* __restrict__ out, int n) {
    __shared__ float sP[GRU_NPB * 81];
    __shared__ float sMz[256], sMr[256], sMh[256];
    __shared__ float sLz[256], sLr[256], sLh[256];
    __shared__ float sBz[16], sBr[16], sBh[16];
    __shared__ float sfcW[32], sfcb[2], sprob[TT];

    int tid = threadIdx.x;
    for (int i = tid; i < 256; i += GRU_NPB) {
        sMz[i] = g_Mz[i]; sMr[i] = g_Mr[i]; sMh[i] = g_Mh[i];
        sLz[i] = Lz[256 + i]; sLr[i] = Lr[256 + i]; sLh[i] = Lh[256 + i];
    }
    if (tid < 16) { sBz[tid] = g_Bz[tid]; sBr[tid] = g_Br[tid]; sBh[tid] = g_Bh[tid]; }
    if (tid < 32) sfcW[tid] = fcW[tid];
    if (tid < 2)  sfcb[tid] = fcb[tid];
    if (tid == 0) {
        float m = att[0];
        for (int t = 1; t < TT; t++) m = fmaxf(m, att[t]);
        float ex[TT]; float s = 0.f;
        for (int t = 0; t < TT; t++) { ex[t] = expf(att[t] - m); s += ex[t]; }
        for (int t = 0; t < TT; t++) sprob[t] = ex[t] / s;
    }
    int base = blockIdx.x * GRU_NPB;
    for (int i = tid; i < GRU_NPB * (FSTRIDE / 2); i += GRU_NPB) {
        int nd = i / (FSTRIDE / 2), c2 = i - nd * (FSTRIDE / 2);
        int g = base + nd;
        float2 f = make_float2(0.f, 0.f);
        if (g < n) {
            unsigned u = __ldg((const unsigned*)(P + (size_t)g * FSTRIDE) + c2);
            f = __half22float2(bits_h2u(u));
        }
        sP[nd * 81 + 2 * c2]     = f.x;
        sP[nd * 81 + 2 * c2 + 1] = f.y;
    }
    __syncthreads();

    int node = base + tid;
    if (node >= n) return;
    const float* myP = &sP[tid * 81];

    float H[16], Hacc[16];
#pragma unroll
    for (int h = 0; h < 16; h++) { H[h] = 0.f; Hacc[h] = 0.f; }

#pragma unroll 1
    for (int t = 0; t < TT; t++) {
        float p[16];
#pragma unroll
        for (int k = 0; k < 16; k++) p[k] = myP[t * 16 + k];

        float a[16];
#pragma unroll
        for (int h = 0; h < 16; h++) a[h] = sBz[h];
#pragma unroll
        for (int k = 0; k < 16; k++) {
            float pk = p[k], hk = H[k];
#pragma unroll
            for (int h = 0; h < 16; h++)
                a[h] += pk * sMz[k * 16 + h] + hk * sLz[k * 16 + h];
        }
        float Zg[16];
#pragma unroll
        for (int h = 0; h < 16; h++) Zg[h] = fast_sig(a[h]);

#pragma unroll
        for (int h = 0; h < 16; h++) a[h] = sBr[h];
#pragma unroll
        for (int k = 0; k < 16; k++) {
            float pk = p[k], hk = H[k];
#pragma unroll
            for (int h = 0; h < 16; h++)
                a[h] += pk * sMr[k * 16 + h] + hk * sLr[k * 16 + h];
        }
        float Rg[16];
#pragma unroll
        for (int h = 0; h < 16; h++) Rg[h] = fast_sig(a[h]);

#pragma unroll
        for (int h = 0; h < 16; h++) a[h] = sBh[h];
#pragma unroll
        for (int k = 0; k < 16; k++) {
            float pk = p[k], hr = H[k] * Rg[k];
#pragma unroll
            for (int h = 0; h < 16; h++)
                a[h] += pk * sMh[k * 16 + h] + hr * sLh[k * 16 + h];
        }
#pragma unroll
        for (int h = 0; h < 16; h++) {
            float ht = fast_tanh(a[h]);
            H[h] = Zg[h] * H[h] + (1.f - Zg[h]) * ht;
            Hacc[h] = fmaf(sprob[t], H[h], Hacc[h]);
        }
    }

    float l0 = sfcb[0], l1 = sfcb[1];
#pragma unroll
    for (int h = 0; h < 16; h++) {
        l0 = fmaf(Hacc[h], sfcW[h * 2 + 0], l0);
        l1 = fmaf(Hacc[h], sfcW[h * 2 + 1], l1);
    }
    float m = fmaxf(l0, l1);
    float lse = m + logf(expf(l0 - m) + expf(l1 - m));
    out[(size_t)node * 2 + 0] = l0 - lse;
    out[(size_t)node * 2 + 1] = l1 - lse;
}

// ---------------- launch ----------------
extern "C" void kernel_launch(void* const* d_in, const int* in_sizes, int n_in,
                              void* d_out, int out_size) {
    const float* x   = (const float*)d_in[0];
    const int*   src = (const int*)d_in[1];
    const int*   dst = (const int*)d_in[2];
    const float* W1  = (const float*)d_in[3];
    const float* b1  = (const float*)d_in[4];
    const float* W2  = (const float*)d_in[5];
    const float* b2  = (const float*)d_in[6];
    const float* Wz  = (const float*)d_in[7];
    const float* bz  = (const float*)d_in[8];
    const float* Wr  = (const float*)d_in[9];
    const float* br  = (const float*)d_in[10];
    const float* Wh  = (const float*)d_in[11];
    const float* bh  = (const float*)d_in[12];
    const float* Lz  = (const float*)d_in[13];
    const float* lz  = (const float*)d_in[14];
    const float* Lr  = (const float*)d_in[15];
    const float* lr  = (const float*)d_in[16];
    const float* Lh  = (const float*)d_in[17];
    const float* lh  = (const float*)d_in[18];
    const float* att = (const float*)d_in[19];
    const float* fcW = (const float*)d_in[20];
    const float* fcb = (const float*)d_in[21];

    int n = in_sizes[0] / (TT * FIN);
    int e = in_sizes[1];

    void* p;
    cudaGetSymbolAddress(&p, g_cnt);     int*    cnt    = (int*)p;
    cudaGetSymbolAddress(&p, g_deg);     int*    degv   = (int*)p;
    cudaGetSymbolAddress(&p, g_row);     int*    rowp   = (int*)p;
    cudaGetSymbolAddress(&p, g_dinv);    float*  dinv   = (float*)p;
    cudaGetSymbolAddress(&p, g_edge);    int2*   edge   = (int2*)p;
    cudaGetSymbolAddress(&p, g_xT);      __half* xT     = (__half*)p;
    cudaGetSymbolAddress(&p, g_h1);      __half* h1     = (__half*)p;
    cudaGetSymbolAddress(&p, g_feats);   __half* feats  = (__half*)p;
    cudaGetSymbolAddress(&p, g_P);       __half* P      = (__half*)p;

    int prep0_threads = (e > n * XREAL) ? e : n * XREAL;
    int prop_blocks = (n + 7) / 8;

    // 0: fused degree count + x transpose (fp16)
    kprep0<<<(prep0_threads + 255) / 256, 256>>>(dst, cnt, x, xT, n, e);
    // 1: merged offsets + fill (resident grid, software grid barrier inside)
    kbuild<<<KB_BLOCKS, 256>>>(src, dst, cnt, edge, n, e);
    // 2: h1 = relu((S x) @ W1 + b1)
    kprop<XSTRIDE, 13, FIN, 1><<<prop_blocks, 256>>>(xT, h1, rowp, degv, edge, dinv, W1, b1, n);
    // 3: feats = relu((S h1) @ W2 + b2)     <-- profiled slot this round
    kprop<FSTRIDE, 20, HID, 1><<<prop_blocks, 256>>>(h1, feats, rowp, degv, edge, dinv, W2, b2, n);
    // 4: P = S feats (half out, shared by all three GRU gate GCNs)
    kprop<FSTRIDE, 20, HID, 0><<<prop_blocks, 256>>>(feats, P, rowp, degv, edge, dinv, W2, b2, n);
    // 5: fold GRU gate weights
    kprepG<<<1, 256>>>(Wz, bz, Wr, br, Wh, bh, Lz, lz, Lr, lr, Lh, lh);
    // 6: GRU + attention + FC + log_softmax
    kgru<<<(n + GRU_NPB - 1) / GRU_NPB, GRU_NPB>>>(P, Lz, Lr, Lh, att, fcW, fcb,
                                                   (float*)d_out, n);
}

// round 7
// speedup vs baseline: 1.1186x; 1.1186x over previous
#include <cuda_runtime.h>
#include <cuda_fp16.h>
#include <math.h>
#include <stdint.h>

// Problem constants (fixed by the dataset)
#define TT 5
#define FIN 10
#define HID 16
#define MAXN 100000
#define MAXE 3200000
#define XSTRIDE 52        // padded T*FIN in halves (50 -> 52; pad stays zero)
#define XREAL  50
#define FSTRIDE 80        // T*HID

// ---------------- device scratch (static: no allocation allowed) ----------------
__device__ int    g_cnt[MAXN];         // zero at load; re-zeroed each call
__device__ int    g_deg[MAXN];
__device__ int    g_row[MAXN];
__device__ int    g_cursor[MAXN];
__device__ int    g_total;
__device__ float  g_dis[MAXN];
__device__ float  g_dinv[MAXN];
__device__ __align__(16) int2   g_edge[MAXE];   // .x = src, .y = half2(w,w) bits
__device__ __align__(16) __half g_xT[(size_t)MAXN * XSTRIDE];
__device__ __align__(16) __half g_h1[(size_t)MAXN * FSTRIDE];
__device__ __align__(16) __half g_feats[(size_t)MAXN * FSTRIDE];
__device__ __align__(16) __half g_P[(size_t)MAXN * FSTRIDE];
__device__ float  g_Mz[256], g_Mr[256], g_Mh[256];
__device__ float  g_Bz[16],  g_Br[16],  g_Bh[16];

__device__ __forceinline__ __half2 bits_h2(int b) {
    return *reinterpret_cast<__half2*>(&b);
}
__device__ __forceinline__ __half2 bits_h2u(unsigned b) {
    return *reinterpret_cast<__half2*>(&b);
}
__device__ __forceinline__ float fast_tanh(float x) {
    float r;
    asm("tanh.approx.f32 %0, %1;" : "=f"(r) : "f"(x));
    return r;
}
__device__ __forceinline__ float fast_sig(float x) {
    return fmaf(0.5f, fast_tanh(0.5f * x), 0.5f);
}
// packed fp32x2 helpers (Blackwell FFMA2 — PTX-only)
__device__ __forceinline__ unsigned long long pack2(float lo, float hi) {
    unsigned long long r;
    asm("mov.b64 %0, {%1, %2};" : "=l"(r) : "f"(lo), "f"(hi));
    return r;
}
__device__ __forceinline__ void unpack2(float& lo, float& hi, unsigned long long v) {
    asm("mov.b64 {%0, %1}, %2;" : "=f"(lo), "=f"(hi) : "l"(v));
}
__device__ __forceinline__ unsigned long long fma2(unsigned long long a,
                                                   unsigned long long b,
                                                   unsigned long long c) {
    unsigned long long d;
    asm("fma.rn.f32x2 %0, %1, %2, %3;" : "=l"(d) : "l"(a), "l"(b), "l"(c));
    return d;
}

// ---------------- stage 0: fused degree count + x transpose (fp16) --------------
__global__ void kprep0(const int* __restrict__ dst, int* cnt,
                       const float* __restrict__ x, __half* __restrict__ xT,
                       int n, int e) {
    int i = blockIdx.x * blockDim.x + threadIdx.x;
    if (i == 0) g_total = 0;
    if (i < e) atomicAdd(&cnt[dst[i]], 1);
    if (i < n * XREAL) {
        int node = i / XREAL;
        int c = i - node * XREAL;
        int t = c / FIN;
        int f = c - t * FIN;
        xT[(size_t)node * XSTRIDE + c] =
            __float2half(x[((size_t)t * n + node) * FIN + f]);
    }
}

// per-block scan + single atomic -> contiguous (unordered) slices per node
__global__ __launch_bounds__(256) void koffsets(int* cnt, int n) {
    __shared__ int sh[256];
    __shared__ int sbase;
    int tid = threadIdx.x;
    int i = blockIdx.x * 256 + tid;
    int deg = (i < n) ? cnt[i] : 0;
    sh[tid] = deg;
    __syncthreads();
    for (int off = 1; off < 256; off <<= 1) {
        int t = (tid >= off) ? sh[tid - off] : 0;
        __syncthreads();
        sh[tid] += t;
        __syncthreads();
    }
    if (tid == 255) sbase = atomicAdd(&g_total, sh[255]);
    __syncthreads();
    int start = sbase + sh[tid] - deg;
    if (i < n) {
        g_row[i]    = start;
        g_cursor[i] = start;
        g_deg[i]    = deg;
        cnt[i]      = 0;                 // restore for next replay
        float d = (float)deg + 1.0f;
        g_dis[i]  = rsqrtf(d);
        g_dinv[i] = 1.0f / d;
    }
}

__global__ void kfill(const int* __restrict__ src, const int* __restrict__ dst,
                      const float* __restrict__ dis, int* cursor, int2* edge, int e) {
    int i = blockIdx.x * blockDim.x + threadIdx.x;
    if (i < e) {
        int s = src[i], d = dst[i];
        int pos = atomicAdd(&cursor[d], 1);
        __half2 h2 = __float2half2_rn(dis[s] * dis[d]);
        edge[pos] = make_int2(s, *reinterpret_cast<int*>(&h2));
    }
}

// ---------------- propagation, hfma2 accumulate, no shfl (round-5 proven) -------
// warp per destination node. Lane ll (clamped to NLOAD-1) owns 4 halves
// [4*ll, 4*ll+4) of the row, loaded as one uint2. All lanes walk the edge
// list with uniform int2 loads (broadcast). 4 independent hfma2 chains.
// MODE 1: out(half) = relu((S in) @ W + b) per time slice (stride FSTRIDE).
// MODE 0: out(half) = S in (stride FSTRIDE).
template <int STRIDE_H, int NLOAD, int FIN_IN, int MODE>
__global__ __launch_bounds__(256) void kprop(const __half* __restrict__ in,
                                             __half* __restrict__ out,
                                             const int* __restrict__ rowp,
                                             const int* __restrict__ degv,
                                             const int2* __restrict__ edge,
                                             const float* __restrict__ dinv,
                                             const float* __restrict__ Wm,
                                             const float* __restrict__ bm, int n) {
    __shared__ float sAgg[MODE ? 8 : 1][MODE ? NLOAD * 4 : 4];
    __shared__ float sW[MODE ? FIN_IN * 16 : 1];
    __shared__ float sB[MODE ? 16 : 1];
    if (MODE) {
        for (int i = threadIdx.x; i < FIN_IN * 16; i += blockDim.x) sW[i] = Wm[i];
        if (threadIdx.x < 16) sB[threadIdx.x] = bm[threadIdx.x];
        __syncthreads();
    }
    int wwid = threadIdx.x >> 5;
    int node = (blockIdx.x << 3) + wwid;
    if (node >= n) return;
    int lane = threadIdx.x & 31;
    int ll = (lane < NLOAD) ? lane : (NLOAD - 1);   // clamp; extras discarded
    bool act = lane < NLOAD;

    __half2 zero2 = __float2half2_rn(0.f);
    __half2 a0x = zero2, a0y = zero2, a1x = zero2, a1y = zero2;
    __half2 a2x = zero2, a2y = zero2, a3x = zero2, a3y = zero2;

    int j = rowp[node];
    int end = j + degv[node];

    for (; j + 4 <= end; j += 4) {
        int2 e0 = __ldg(edge + j);
        int2 e1 = __ldg(edge + j + 1);
        int2 e2 = __ldg(edge + j + 2);
        int2 e3 = __ldg(edge + j + 3);
        uint2 q0 = __ldg((const uint2*)(in + (size_t)e0.x * STRIDE_H) + ll);
        uint2 q1 = __ldg((const uint2*)(in + (size_t)e1.x * STRIDE_H) + ll);
        uint2 q2 = __ldg((const uint2*)(in + (size_t)e2.x * STRIDE_H) + ll);
        uint2 q3 = __ldg((const uint2*)(in + (size_t)e3.x * STRIDE_H) + ll);
        __half2 w0 = bits_h2(e0.y), w1 = bits_h2(e1.y);
        __half2 w2 = bits_h2(e2.y), w3 = bits_h2(e3.y);
        a0x = __hfma2(w0, bits_h2u(q0.x), a0x);
        a0y = __hfma2(w0, bits_h2u(q0.y), a0y);
        a1x = __hfma2(w1, bits_h2u(q1.x), a1x);
        a1y = __hfma2(w1, bits_h2u(q1.y), a1y);
        a2x = __hfma2(w2, bits_h2u(q2.x), a2x);
        a2y = __hfma2(w2, bits_h2u(q2.y), a2y);
        a3x = __hfma2(w3, bits_h2u(q3.x), a3x);
        a3y = __hfma2(w3, bits_h2u(q3.y), a3y);
    }
    for (; j < end; j++) {
        int2 e0 = __ldg(edge + j);
        uint2 q0 = __ldg((const uint2*)(in + (size_t)e0.x * STRIDE_H) + ll);
        __half2 w0 = bits_h2(e0.y);
        a0x = __hfma2(w0, bits_h2u(q0.x), a0x);
        a0y = __hfma2(w0, bits_h2u(q0.y), a0y);
    }

    // merge chains in fp32 + fp32 self-loop
    float di = dinv[node];
    uint2 sq = __ldg((const uint2*)(in + (size_t)node * STRIDE_H) + ll);
    float2 s01 = __half22float2(bits_h2u(sq.x));
    float2 s23 = __half22float2(bits_h2u(sq.y));
    float2 c0, c1, c2, c3;
    c0 = __half22float2(a0x); c1 = __half22float2(a1x);
    c2 = __half22float2(a2x); c3 = __half22float2(a3x);
    float f0 = (c0.x + c1.x) + (c2.x + c3.x) + di * s01.x;
    float f1 = (c0.y + c1.y) + (c2.y + c3.y) + di * s01.y;
    c0 = __half22float2(a0y); c1 = __half22float2(a1y);
    c2 = __half22float2(a2y); c3 = __half22float2(a3y);
    float f2 = (c0.x + c1.x) + (c2.x + c3.x) + di * s23.x;
    float f3 = (c0.y + c1.y) + (c2.y + c3.y) + di * s23.y;

    if (!MODE) {
        if (act) {
            __half2 o01 = __floats2half2_rn(f0, f1);
            __half2 o23 = __floats2half2_rn(f2, f3);
            uint2 pk;
            pk.x = *reinterpret_cast<unsigned*>(&o01);
            pk.y = *reinterpret_cast<unsigned*>(&o23);
            *((uint2*)(out + (size_t)node * FSTRIDE) + lane) = pk;
        }
        return;
    }

    // stage the aggregate, then per-slice dense transform + relu + fp16 pack
    if (act) {
        float4 fv = make_float4(f0, f1, f2, f3);
        *(float4*)&sAgg[wwid][lane * 4] = fv;
    }
    __syncwarp();
    if (lane < 20) {
        int c = lane * 4;         // 20 lanes x 4 outputs = 80
        int t = c >> 4;
        int h = c & 15;
        float o0 = sB[h], o1 = sB[h + 1], o2 = sB[h + 2], o3 = sB[h + 3];
#pragma unroll
        for (int f = 0; f < FIN_IN; f++) {
            float a = sAgg[wwid][t * FIN_IN + f];
            o0 = fmaf(a, sW[f * 16 + h],     o0);
            o1 = fmaf(a, sW[f * 16 + h + 1], o1);
            o2 = fmaf(a, sW[f * 16 + h + 2], o2);
            o3 = fmaf(a, sW[f * 16 + h + 3], o3);
        }
        __half2 p01 = __floats2half2_rn(fmaxf(o0, 0.f), fmaxf(o1, 0.f));
        __half2 p23 = __floats2half2_rn(fmaxf(o2, 0.f), fmaxf(o3, 0.f));
        uint2 pk;
        pk.x = *reinterpret_cast<unsigned*>(&p01);
        pk.y = *reinterpret_cast<unsigned*>(&p23);
        *((uint2*)(out + (size_t)node * FSTRIDE) + lane) = pk;
    }
}

// ---------------- fold gate matmuls: M* = W* @ L*[0:16], B* = b*@L*[0:16] + l* ----
__global__ void kprepG(const float* Wz, const float* bz, const float* Wr, const float* br,
                       const float* Wh, const float* bh,
                       const float* Lz, const float* lz, const float* Lr, const float* lr,
                       const float* Lh, const float* lh) {
    int tid = threadIdx.x;  // 256
    int k = tid >> 4, h = tid & 15;
    float mz = 0.f, mr = 0.f, mh = 0.f;
#pragma unroll
    for (int j = 0; j < 16; j++) {
        mz = fmaf(Wz[k * 16 + j], Lz[j * 16 + h], mz);
        mr = fmaf(Wr[k * 16 + j], Lr[j * 16 + h], mr);
        mh = fmaf(Wh[k * 16 + j], Lh[j * 16 + h], mh);
    }
    g_Mz[tid] = mz; g_Mr[tid] = mr; g_Mh[tid] = mh;
    if (tid < 16) {
        float az = lz[tid], ar = lr[tid], ah = lh[tid];
#pragma unroll
        for (int j = 0; j < 16; j++) {
            az = fmaf(bz[j], Lz[j * 16 + tid], az);
            ar = fmaf(br[j], Lr[j * 16 + tid], ar);
            ah = fmaf(bh[j], Lh[j * 16 + tid], ah);
        }
        g_Bz[tid] = az; g_Br[tid] = ar; g_Bh[tid] = ah;
    }
}

// ---------------- GRU (packed f32x2 FFMA2) + attention + FC + log_softmax -------
#define GRU_NPB 96
__global__ __launch_bounds__(GRU_NPB) void kgru(const __half* __restrict__ P,
                                                const float* __restrict__ Lz,
                                                const float* __restrict__ Lr,
                                                const float* __restrict__ Lh,
                                                const float* __restrict__ att,
                                                const float* __restrict__ fcW,
                                                const float* __restrict__ fcb,
                                                float* __restrict__ out, int n) {
    // gate matrices packed as (h, h+1) fp32 pairs: index [k*8 + j], j = h/2
    __shared__ unsigned long long sM2z[128], sM2r[128], sM2h[128];
    __shared__ unsigned long long sL2z[128], sL2r[128], sL2h[128];
    __shared__ unsigned long long sB2z[8], sB2r[8], sB2h[8];
    __shared__ float sP[GRU_NPB * 81];
    __shared__ float sfcW[32], sfcb[2], sprob[TT];

    int tid = threadIdx.x;
    for (int i = tid; i < 128; i += GRU_NPB) {
        int k = i >> 3, j = i & 7;
        int gi = k * 16 + 2 * j;
        sM2z[i] = pack2(g_Mz[gi], g_Mz[gi + 1]);
        sM2r[i] = pack2(g_Mr[gi], g_Mr[gi + 1]);
        sM2h[i] = pack2(g_Mh[gi], g_Mh[gi + 1]);
        sL2z[i] = pack2(Lz[256 + gi], Lz[256 + gi + 1]);
        sL2r[i] = pack2(Lr[256 + gi], Lr[256 + gi + 1]);
        sL2h[i] = pack2(Lh[256 + gi], Lh[256 + gi + 1]);
    }
    if (tid < 8) {
        sB2z[tid] = pack2(g_Bz[2 * tid], g_Bz[2 * tid + 1]);
        sB2r[tid] = pack2(g_Br[2 * tid], g_Br[2 * tid + 1]);
        sB2h[tid] = pack2(g_Bh[2 * tid], g_Bh[2 * tid + 1]);
    }
    if (tid < 32) sfcW[tid] = fcW[tid];
    if (tid < 2)  sfcb[tid] = fcb[tid];
    if (tid == 0) {
        float m = att[0];
        for (int t = 1; t < TT; t++) m = fmaxf(m, att[t]);
        float ex[TT]; float s = 0.f;
        for (int t = 0; t < TT; t++) { ex[t] = expf(att[t] - m); s += ex[t]; }
        for (int t = 0; t < TT; t++) sprob[t] = ex[t] / s;
    }
    int base = blockIdx.x * GRU_NPB;
    for (int i = tid; i < GRU_NPB * (FSTRIDE / 2); i += GRU_NPB) {
        int nd = i / (FSTRIDE / 2), c2 = i - nd * (FSTRIDE / 2);
        int g = base + nd;
        float2 f = make_float2(0.f, 0.f);
        if (g < n) {
            unsigned u = __ldg((const unsigned*)(P + (size_t)g * FSTRIDE) + c2);
            f = __half22float2(bits_h2u(u));
        }
        sP[nd * 81 + 2 * c2]     = f.x;
        sP[nd * 81 + 2 * c2 + 1] = f.y;
    }
    __syncthreads();

    int node = base + tid;
    if (node >= n) return;
    const float* myP = &sP[tid * 81];

    float H[16], Hacc[16];
#pragma unroll
    for (int h = 0; h < 16; h++) { H[h] = 0.f; Hacc[h] = 0.f; }

#pragma unroll 1
    for (int t = 0; t < TT; t++) {
        unsigned long long pk2[16], hk2[16];
#pragma unroll
        for (int k = 0; k < 16; k++) {
            float pk = myP[t * 16 + k];
            pk2[k] = pack2(pk, pk);
            hk2[k] = pack2(H[k], H[k]);
        }

        unsigned long long acc[8];
        float a[16];
        // Z gate
#pragma unroll
        for (int j = 0; j < 8; j++) acc[j] = sB2z[j];
#pragma unroll
        for (int k = 0; k < 16; k++) {
#pragma unroll
            for (int j = 0; j < 8; j++) {
                acc[j] = fma2(pk2[k], sM2z[k * 8 + j], acc[j]);
                acc[j] = fma2(hk2[k], sL2z[k * 8 + j], acc[j]);
            }
        }
        float Zg[16];
#pragma unroll
        for (int j = 0; j < 8; j++) unpack2(a[2 * j], a[2 * j + 1], acc[j]);
#pragma unroll
        for (int h = 0; h < 16; h++) Zg[h] = fast_sig(a[h]);

        // R gate
#pragma unroll
        for (int j = 0; j < 8; j++) acc[j] = sB2r[j];
#pragma unroll
        for (int k = 0; k < 16; k++) {
#pragma unroll
            for (int j = 0; j < 8; j++) {
                acc[j] = fma2(pk2[k], sM2r[k * 8 + j], acc[j]);
                acc[j] = fma2(hk2[k], sL2r[k * 8 + j], acc[j]);
            }
        }
        float Rg[16];
#pragma unroll
        for (int j = 0; j < 8; j++) unpack2(a[2 * j], a[2 * j + 1], acc[j]);
#pragma unroll
        for (int h = 0; h < 16; h++) Rg[h] = fast_sig(a[h]);

        // candidate gate: uses H*Rg
#pragma unroll
        for (int k = 0; k < 16; k++) {
            float hr = H[k] * Rg[k];
            hk2[k] = pack2(hr, hr);
        }
#pragma unroll
        for (int j = 0; j < 8; j++) acc[j] = sB2h[j];
#pragma unroll
        for (int k = 0; k < 16; k++) {
#pragma unroll
            for (int j = 0; j < 8; j++) {
                acc[j] = fma2(pk2[k], sM2h[k * 8 + j], acc[j]);
                acc[j] = fma2(hk2[k], sL2h[k * 8 + j], acc[j]);
            }
        }
#pragma unroll
        for (int j = 0; j < 8; j++) unpack2(a[2 * j], a[2 * j + 1], acc[j]);
#pragma unroll
        for (int h = 0; h < 16; h++) {
            float ht = fast_tanh(a[h]);
            H[h] = Zg[h] * H[h] + (1.f - Zg[h]) * ht;
            Hacc[h] = fmaf(sprob[t], H[h], Hacc[h]);
        }
    }

    float l0 = sfcb[0], l1 = sfcb[1];
#pragma unroll
    for (int h = 0; h < 16; h++) {
        l0 = fmaf(Hacc[h], sfcW[h * 2 + 0], l0);
        l1 = fmaf(Hacc[h], sfcW[h * 2 + 1], l1);
    }
    float m = fmaxf(l0, l1);
    float lse = m + logf(expf(l0 - m) + expf(l1 - m));
    out[(size_t)node * 2 + 0] = l0 - lse;
    out[(size_t)node * 2 + 1] = l1 - lse;
}

// ---------------- launch ----------------
extern "C" void kernel_launch(void* const* d_in, const int* in_sizes, int n_in,
                              void* d_out, int out_size) {
    const float* x   = (const float*)d_in[0];
    const int*   src = (const int*)d_in[1];
    const int*   dst = (const int*)d_in[2];
    const float* W1  = (const float*)d_in[3];
    const float* b1  = (const float*)d_in[4];
    const float* W2  = (const float*)d_in[5];
    const float* b2  = (const float*)d_in[6];
    const float* Wz  = (const float*)d_in[7];
    const float* bz  = (const float*)d_in[8];
    const float* Wr  = (const float*)d_in[9];
    const float* br  = (const float*)d_in[10];
    const float* Wh  = (const float*)d_in[11];
    const float* bh  = (const float*)d_in[12];
    const float* Lz  = (const float*)d_in[13];
    const float* lz  = (const float*)d_in[14];
    const float* Lr  = (const float*)d_in[15];
    const float* lr  = (const float*)d_in[16];
    const float* Lh  = (const float*)d_in[17];
    const float* lh  = (const float*)d_in[18];
    const float* att = (const float*)d_in[19];
    const float* fcW = (const float*)d_in[20];
    const float* fcb = (const float*)d_in[21];

    int n = in_sizes[0] / (TT * FIN);
    int e = in_sizes[1];

    void* p;
    cudaGetSymbolAddress(&p, g_cnt);     int*    cnt    = (int*)p;
    cudaGetSymbolAddress(&p, g_deg);     int*    degv   = (int*)p;
    cudaGetSymbolAddress(&p, g_row);     int*    rowp   = (int*)p;
    cudaGetSymbolAddress(&p, g_cursor);  int*    cursor = (int*)p;
    cudaGetSymbolAddress(&p, g_dis);     float*  dis    = (float*)p;
    cudaGetSymbolAddress(&p, g_dinv);    float*  dinv   = (float*)p;
    cudaGetSymbolAddress(&p, g_edge);    int2*   edge   = (int2*)p;
    cudaGetSymbolAddress(&p, g_xT);      __half* xT     = (__half*)p;
    cudaGetSymbolAddress(&p, g_h1);      __half* h1     = (__half*)p;
    cudaGetSymbolAddress(&p, g_feats);   __half* feats  = (__half*)p;
    cudaGetSymbolAddress(&p, g_P);       __half* P      = (__half*)p;

    int nb256_n = (n + 255) / 256;
    int nb256_e = (e + 255) / 256;
    int prep0_threads = (e > n * XREAL) ? e : n * XREAL;
    int prop_blocks = (n + 7) / 8;

    // 0: fused degree count + x transpose (fp16)
    kprep0<<<(prep0_threads + 255) / 256, 256>>>(dst, cnt, x, xT, n, e);
    // 1: offsets + norms
    koffsets<<<nb256_n, 256>>>(cnt, n);
    // 2: fill edge list (weights packed half2)
    kfill<<<nb256_e, 256>>>(src, dst, dis, cursor, edge, e);
    // 3: h1 = relu((S x) @ W1 + b1)      <-- profiled slot (sanity: ~87us)
    kprop<XSTRIDE, 13, FIN, 1><<<prop_blocks, 256>>>(xT, h1, rowp, degv, edge, dinv, W1, b1, n);
    // 4: feats = relu((S h1) @ W2 + b2)
    kprop<FSTRIDE, 20, HID, 1><<<prop_blocks, 256>>>(h1, feats, rowp, degv, edge, dinv, W2, b2, n);
    // 5: P = S feats (half out, shared by all three GRU gate GCNs)
    kprop<FSTRIDE, 20, HID, 0><<<prop_blocks, 256>>>(feats, P, rowp, degv, edge, dinv, W2, b2, n);
    // 6: fold GRU gate weights
    kprepG<<<1, 256>>>(Wz, bz, Wr, br, Wh, bh, Lz, lz, Lr, lr, Lh, lh);
    // 7: GRU (FFMA2) + attention + FC + log_softmax
    kgru<<<(n + GRU_NPB - 1) / GRU_NPB, GRU_NPB>>>(P, Lz, Lr, Lh, att, fcW, fcb,
                                                   (float*)d_out, n);
}

// round 8
// speedup vs baseline: 1.1415x; 1.0205x over previous
#include <cuda_runtime.h>
#include <cuda_fp16.h>
#include <math.h>
#include <stdint.h>

// Problem constants (fixed by the dataset)
#define TT 5
#define FIN 10
#define HID 16
#define MAXN 100000
#define MAXE 3200000
#define XSTRIDE 64        // xT row stride in halves -> 128B aligned rows
#define XREAL  50
#define F8STRIDE 128      // fp8 feature row stride in BYTES (80 data + pad)
#define FSTRIDE 80        // P row stride in halves (fp16)

// ---------------- device scratch (static: no allocation allowed) ----------------
__device__ int    g_cnt[MAXN];         // zero at load; re-zeroed each call
__device__ int    g_deg[MAXN];
__device__ int    g_row[MAXN];
__device__ int    g_cursor[MAXN];
__device__ int    g_total;
__device__ float  g_dis[MAXN];
__device__ float  g_dinv[MAXN];
__device__ __align__(16) int2          g_edge[MAXE];   // .x = src, .y = half2(w,w) bits
__device__ __align__(16) __half        g_xT[(size_t)MAXN * XSTRIDE];      // pad cols stay 0
__device__ __align__(16) unsigned char g_h1[(size_t)MAXN * F8STRIDE];     // e4m3
__device__ __align__(16) unsigned char g_feats[(size_t)MAXN * F8STRIDE];  // e4m3
__device__ __align__(16) __half        g_P[(size_t)MAXN * FSTRIDE];
__device__ float  g_Mz[256], g_Mr[256], g_Mh[256];
__device__ float  g_Bz[16],  g_Br[16],  g_Bh[16];

__device__ __forceinline__ __half2 bits_h2(int b) {
    return *reinterpret_cast<__half2*>(&b);
}
__device__ __forceinline__ __half2 bits_h2u(unsigned b) {
    return *reinterpret_cast<__half2*>(&b);
}
__device__ __forceinline__ float fast_tanh(float x) {
    float r;
    asm("tanh.approx.f32 %0, %1;" : "=f"(r) : "f"(x));
    return r;
}
__device__ __forceinline__ float fast_sig(float x) {
    return fmaf(0.5f, fast_tanh(0.5f * x), 0.5f);
}
// packed fp32x2 helpers (Blackwell FFMA2 — PTX-only)
__device__ __forceinline__ unsigned long long pack2(float lo, float hi) {
    unsigned long long r;
    asm("mov.b64 %0, {%1, %2};" : "=l"(r) : "f"(lo), "f"(hi));
    return r;
}
__device__ __forceinline__ void unpack2(float& lo, float& hi, unsigned long long v) {
    asm("mov.b64 {%0, %1}, %2;" : "=f"(lo), "=f"(hi) : "l"(v));
}
__device__ __forceinline__ unsigned long long fma2(unsigned long long a,
                                                   unsigned long long b,
                                                   unsigned long long c) {
    unsigned long long d;
    asm("fma.rn.f32x2 %0, %1, %2, %3;" : "=l"(d) : "l"(a), "l"(b), "l"(c));
    return d;
}
// fp8 e4m3 pack/unpack
__device__ __forceinline__ unsigned pack_e4m3x4(float a, float b, float c, float d) {
    unsigned short lo, hi;
    asm("cvt.rn.satfinite.e4m3x2.f32 %0, %1, %2;" : "=h"(lo) : "f"(b), "f"(a));
    asm("cvt.rn.satfinite.e4m3x2.f32 %0, %1, %2;" : "=h"(hi) : "f"(d), "f"(c));
    return (unsigned)lo | ((unsigned)hi << 16);
}
__device__ __forceinline__ void unpack_e4m3x4(unsigned q, __half2& p01, __half2& p23) {
    unsigned a, b;
    asm("{\n\t"
        ".reg .b16 lo, hi;\n\t"
        "mov.b32 {lo, hi}, %2;\n\t"
        "cvt.rn.f16x2.e4m3x2 %0, lo;\n\t"
        "cvt.rn.f16x2.e4m3x2 %1, hi;\n\t"
        "}" : "=r"(a), "=r"(b) : "r"(q));
    p01 = bits_h2u(a);
    p23 = bits_h2u(b);
}

// ---------------- stage 0: fused degree count + x transpose (fp16) --------------
__global__ void kprep0(const int* __restrict__ dst, int* cnt,
                       const float* __restrict__ x, __half* __restrict__ xT,
                       int n, int e) {
    int i = blockIdx.x * blockDim.x + threadIdx.x;
    if (i == 0) g_total = 0;
    if (i < e) atomicAdd(&cnt[dst[i]], 1);
    if (i < n * XREAL) {
        int node = i / XREAL;
        int c = i - node * XREAL;
        int t = c / FIN;
        int f = c - t * FIN;
        xT[(size_t)node * XSTRIDE + c] =
            __float2half(x[((size_t)t * n + node) * FIN + f]);
    }
}

// per-block scan + single atomic -> contiguous (unordered) slices per node
__global__ __launch_bounds__(256) void koffsets(int* cnt, int n) {
    __shared__ int sh[256];
    __shared__ int sbase;
    int tid = threadIdx.x;
    int i = blockIdx.x * 256 + tid;
    int deg = (i < n) ? cnt[i] : 0;
    sh[tid] = deg;
    __syncthreads();
    for (int off = 1; off < 256; off <<= 1) {
        int t = (tid >= off) ? sh[tid - off] : 0;
        __syncthreads();
        sh[tid] += t;
        __syncthreads();
    }
    if (tid == 255) sbase = atomicAdd(&g_total, sh[255]);
    __syncthreads();
    int start = sbase + sh[tid] - deg;
    if (i < n) {
        g_row[i]    = start;
        g_cursor[i] = start;
        g_deg[i]    = deg;
        cnt[i]      = 0;                 // restore for next replay
        float d = (float)deg + 1.0f;
        g_dis[i]  = rsqrtf(d);
        g_dinv[i] = 1.0f / d;
    }
}

__global__ void kfill(const int* __restrict__ src, const int* __restrict__ dst,
                      const float* __restrict__ dis, int* cursor, int2* edge, int e) {
    int i = blockIdx.x * blockDim.x + threadIdx.x;
    if (i < e) {
        int s = src[i], d = dst[i];
        int pos = atomicAdd(&cursor[d], 1);
        __half2 h2 = __float2half2_rn(dis[s] * dis[d]);
        edge[pos] = make_int2(s, *reinterpret_cast<int*>(&h2));
    }
}

// ---------------- stage 2: fp16 gather (1 line/row) -> fp8 transformed output ---
// warp per node. Lanes 0-12 each own 4 halves (uint2). Edge meta via uniform
// int2 loads. 4 hfma2 chains. Epilogue: relu((S x)@W1 + b1) per slice -> fp8.
__global__ __launch_bounds__(256) void kprop_x(const __half* __restrict__ in,
                                               unsigned char* __restrict__ out,
                                               const int* __restrict__ rowp,
                                               const int* __restrict__ degv,
                                               const int2* __restrict__ edge,
                                               const float* __restrict__ dinv,
                                               const float* __restrict__ Wm,
                                               const float* __restrict__ bm, int n) {
    __shared__ float sAgg[8][52];
    __shared__ float sW[FIN * 16];
    __shared__ float sB[16];
    for (int i = threadIdx.x; i < FIN * 16; i += blockDim.x) sW[i] = Wm[i];
    if (threadIdx.x < 16) sB[threadIdx.x] = bm[threadIdx.x];
    __syncthreads();

    int wwid = threadIdx.x >> 5;
    int node = (blockIdx.x << 3) + wwid;
    if (node >= n) return;
    int lane = threadIdx.x & 31;
    int ll = (lane < 13) ? lane : 12;
    bool act = lane < 13;

    __half2 zero2 = __float2half2_rn(0.f);
    __half2 a0x = zero2, a0y = zero2, a1x = zero2, a1y = zero2;
    __half2 a2x = zero2, a2y = zero2, a3x = zero2, a3y = zero2;

    int j = rowp[node];
    int end = j + degv[node];

    for (; j + 4 <= end; j += 4) {
        int2 e0 = __ldg(edge + j);
        int2 e1 = __ldg(edge + j + 1);
        int2 e2 = __ldg(edge + j + 2);
        int2 e3 = __ldg(edge + j + 3);
        uint2 q0 = __ldg((const uint2*)(in + (size_t)e0.x * XSTRIDE) + ll);
        uint2 q1 = __ldg((const uint2*)(in + (size_t)e1.x * XSTRIDE) + ll);
        uint2 q2 = __ldg((const uint2*)(in + (size_t)e2.x * XSTRIDE) + ll);
        uint2 q3 = __ldg((const uint2*)(in + (size_t)e3.x * XSTRIDE) + ll);
        __half2 w0 = bits_h2(e0.y), w1 = bits_h2(e1.y);
        __half2 w2 = bits_h2(e2.y), w3 = bits_h2(e3.y);
        a0x = __hfma2(w0, bits_h2u(q0.x), a0x);
        a0y = __hfma2(w0, bits_h2u(q0.y), a0y);
        a1x = __hfma2(w1, bits_h2u(q1.x), a1x);
        a1y = __hfma2(w1, bits_h2u(q1.y), a1y);
        a2x = __hfma2(w2, bits_h2u(q2.x), a2x);
        a2y = __hfma2(w2, bits_h2u(q2.y), a2y);
        a3x = __hfma2(w3, bits_h2u(q3.x), a3x);
        a3y = __hfma2(w3, bits_h2u(q3.y), a3y);
    }
    for (; j < end; j++) {
        int2 e0 = __ldg(edge + j);
        uint2 q0 = __ldg((const uint2*)(in + (size_t)e0.x * XSTRIDE) + ll);
        __half2 w0 = bits_h2(e0.y);
        a0x = __hfma2(w0, bits_h2u(q0.x), a0x);
        a0y = __hfma2(w0, bits_h2u(q0.y), a0y);
    }

    float di = dinv[node];
    uint2 sq = __ldg((const uint2*)(in + (size_t)node * XSTRIDE) + ll);
    float2 s01 = __half22float2(bits_h2u(sq.x));
    float2 s23 = __half22float2(bits_h2u(sq.y));
    float2 c0, c1, c2, c3;
    c0 = __half22float2(a0x); c1 = __half22float2(a1x);
    c2 = __half22float2(a2x); c3 = __half22float2(a3x);
    float f0 = (c0.x + c1.x) + (c2.x + c3.x) + di * s01.x;
    float f1 = (c0.y + c1.y) + (c2.y + c3.y) + di * s01.y;
    c0 = __half22float2(a0y); c1 = __half22float2(a1y);
    c2 = __half22float2(a2y); c3 = __half22float2(a3y);
    float f2 = (c0.x + c1.x) + (c2.x + c3.x) + di * s23.x;
    float f3 = (c0.y + c1.y) + (c2.y + c3.y) + di * s23.y;

    if (act) {
        float4 fv = make_float4(f0, f1, f2, f3);
        *(float4*)&sAgg[wwid][lane * 4] = fv;
    }
    __syncwarp();
    if (lane < 20) {
        int c = lane * 4;
        int t = c >> 4;
        int h = c & 15;
        float o0 = sB[h], o1 = sB[h + 1], o2 = sB[h + 2], o3 = sB[h + 3];
#pragma unroll
        for (int f = 0; f < FIN; f++) {
            float a = sAgg[wwid][t * FIN + f];
            o0 = fmaf(a, sW[f * 16 + h],     o0);
            o1 = fmaf(a, sW[f * 16 + h + 1], o1);
            o2 = fmaf(a, sW[f * 16 + h + 2], o2);
            o3 = fmaf(a, sW[f * 16 + h + 3], o3);
        }
        unsigned pk = pack_e4m3x4(fmaxf(o0, 0.f), fmaxf(o1, 0.f),
                                  fmaxf(o2, 0.f), fmaxf(o3, 0.f));
        ((unsigned*)(out + (size_t)node * F8STRIDE))[lane] = pk;
    }
}

// ---------------- stage 4/5: fp8 gather (1 line/row) -----------------------------
// MODE 1: out fp8 = relu((S in)@W2 + b2) per slice. MODE 0: out fp16 P = S in.
template <int MODE>
__global__ __launch_bounds__(256) void kprop8(const unsigned char* __restrict__ in,
                                              void* __restrict__ outv,
                                              const int* __restrict__ rowp,
                                              const int* __restrict__ degv,
                                              const int2* __restrict__ edge,
                                              const float* __restrict__ dinv,
                                              const float* __restrict__ Wm,
                                              const float* __restrict__ bm, int n) {
    __shared__ float sAgg[MODE ? 8 : 1][MODE ? 80 : 4];
    __shared__ float sW[MODE ? HID * 16 : 1];
    __shared__ float sB[MODE ? 16 : 1];
    if (MODE) {
        for (int i = threadIdx.x; i < HID * 16; i += blockDim.x) sW[i] = Wm[i];
        if (threadIdx.x < 16) sB[threadIdx.x] = bm[threadIdx.x];
        __syncthreads();
    }
    int wwid = threadIdx.x >> 5;
    int node = (blockIdx.x << 3) + wwid;
    if (node >= n) return;
    int lane = threadIdx.x & 31;
    int ll = (lane < 20) ? lane : 19;
    bool act = lane < 20;

    __half2 zero2 = __float2half2_rn(0.f);
    __half2 a0x = zero2, a0y = zero2, a1x = zero2, a1y = zero2;
    __half2 a2x = zero2, a2y = zero2, a3x = zero2, a3y = zero2;

    int j = rowp[node];
    int end = j + degv[node];

    for (; j + 4 <= end; j += 4) {
        int2 e0 = __ldg(edge + j);
        int2 e1 = __ldg(edge + j + 1);
        int2 e2 = __ldg(edge + j + 2);
        int2 e3 = __ldg(edge + j + 3);
        unsigned q0 = __ldg((const unsigned*)(in + (size_t)e0.x * F8STRIDE) + ll);
        unsigned q1 = __ldg((const unsigned*)(in + (size_t)e1.x * F8STRIDE) + ll);
        unsigned q2 = __ldg((const unsigned*)(in + (size_t)e2.x * F8STRIDE) + ll);
        unsigned q3 = __ldg((const unsigned*)(in + (size_t)e3.x * F8STRIDE) + ll);
        __half2 w0 = bits_h2(e0.y), w1 = bits_h2(e1.y);
        __half2 w2 = bits_h2(e2.y), w3 = bits_h2(e3.y);
        __half2 pa, pb;
        unpack_e4m3x4(q0, pa, pb);
        a0x = __hfma2(w0, pa, a0x); a0y = __hfma2(w0, pb, a0y);
        unpack_e4m3x4(q1, pa, pb);
        a1x = __hfma2(w1, pa, a1x); a1y = __hfma2(w1, pb, a1y);
        unpack_e4m3x4(q2, pa, pb);
        a2x = __hfma2(w2, pa, a2x); a2y = __hfma2(w2, pb, a2y);
        unpack_e4m3x4(q3, pa, pb);
        a3x = __hfma2(w3, pa, a3x); a3y = __hfma2(w3, pb, a3y);
    }
    for (; j < end; j++) {
        int2 e0 = __ldg(edge + j);
        unsigned q0 = __ldg((const unsigned*)(in + (size_t)e0.x * F8STRIDE) + ll);
        __half2 w0 = bits_h2(e0.y);
        __half2 pa, pb;
        unpack_e4m3x4(q0, pa, pb);
        a0x = __hfma2(w0, pa, a0x);
        a0y = __hfma2(w0, pb, a0y);
    }

    // merge chains in fp32 + fp32 self-loop
    float di = dinv[node];
    unsigned sq = __ldg((const unsigned*)(in + (size_t)node * F8STRIDE) + ll);
    __half2 sa, sb;
    unpack_e4m3x4(sq, sa, sb);
    float2 s01 = __half22float2(sa);
    float2 s23 = __half22float2(sb);
    float2 c0, c1, c2, c3;
    c0 = __half22float2(a0x); c1 = __half22float2(a1x);
    c2 = __half22float2(a2x); c3 = __half22float2(a3x);
    float f0 = (c0.x + c1.x) + (c2.x + c3.x) + di * s01.x;
    float f1 = (c0.y + c1.y) + (c2.y + c3.y) + di * s01.y;
    c0 = __half22float2(a0y); c1 = __half22float2(a1y);
    c2 = __half22float2(a2y); c3 = __half22float2(a3y);
    float f2 = (c0.x + c1.x) + (c2.x + c3.x) + di * s23.x;
    float f3 = (c0.y + c1.y) + (c2.y + c3.y) + di * s23.y;

    if (!MODE) {
        if (act) {
            __half2 o01 = __floats2half2_rn(f0, f1);
            __half2 o23 = __floats2half2_rn(f2, f3);
            uint2 pk;
            pk.x = *reinterpret_cast<unsigned*>(&o01);
            pk.y = *reinterpret_cast<unsigned*>(&o23);
            *((uint2*)((__half*)outv + (size_t)node * FSTRIDE) + lane) = pk;
        }
        return;
    }

    if (act) {
        float4 fv = make_float4(f0, f1, f2, f3);
        *(float4*)&sAgg[wwid][lane * 4] = fv;
    }
    __syncwarp();
    if (lane < 20) {
        int c = lane * 4;
        int t = c >> 4;
        int h = c & 15;
        float o0 = sB[h], o1 = sB[h + 1], o2 = sB[h + 2], o3 = sB[h + 3];
#pragma unroll
        for (int f = 0; f < HID; f++) {
            float a = sAgg[wwid][t * HID + f];
            o0 = fmaf(a, sW[f * 16 + h],     o0);
            o1 = fmaf(a, sW[f * 16 + h + 1], o1);
            o2 = fmaf(a, sW[f * 16 + h + 2], o2);
            o3 = fmaf(a, sW[f * 16 + h + 3], o3);
        }
        unsigned pk = pack_e4m3x4(fmaxf(o0, 0.f), fmaxf(o1, 0.f),
                                  fmaxf(o2, 0.f), fmaxf(o3, 0.f));
        ((unsigned*)((unsigned char*)outv + (size_t)node * F8STRIDE))[lane] = pk;
    }
}

// ---------------- fold gate matmuls: M* = W* @ L*[0:16], B* = b*@L*[0:16] + l* ----
__global__ void kprepG(const float* Wz, const float* bz, const float* Wr, const float* br,
                       const float* Wh, const float* bh,
                       const float* Lz, const float* lz, const float* Lr, const float* lr,
                       const float* Lh, const float* lh) {
    int tid = threadIdx.x;  // 256
    int k = tid >> 4, h = tid & 15;
    float mz = 0.f, mr = 0.f, mh = 0.f;
#pragma unroll
    for (int j = 0; j < 16; j++) {
        mz = fmaf(Wz[k * 16 + j], Lz[j * 16 + h], mz);
        mr = fmaf(Wr[k * 16 + j], Lr[j * 16 + h], mr);
        mh = fmaf(Wh[k * 16 + j], Lh[j * 16 + h], mh);
    }
    g_Mz[tid] = mz; g_Mr[tid] = mr; g_Mh[tid] = mh;
    if (tid < 16) {
        float az = lz[tid], ar = lr[tid], ah = lh[tid];
#pragma unroll
        for (int j = 0; j < 16; j++) {
            az = fmaf(bz[j], Lz[j * 16 + tid], az);
            ar = fmaf(br[j], Lr[j * 16 + tid], ar);
            ah = fmaf(bh[j], Lh[j * 16 + tid], ah);
        }
        g_Bz[tid] = az; g_Br[tid] = ar; g_Bh[tid] = ah;
    }
}

// ---------------- GRU (packed f32x2 FFMA2) + attention + FC + log_softmax -------
#define GRU_NPB 96
__global__ __launch_bounds__(GRU_NPB) void kgru(const __half* __restrict__ P,
                                                const float* __restrict__ Lz,
                                                const float* __restrict__ Lr,
                                                const float* __restrict__ Lh,
                                                const float* __restrict__ att,
                                                const float* __restrict__ fcW,
                                                const float* __restrict__ fcb,
                                                float* __restrict__ out, int n) {
    __shared__ unsigned long long sM2z[128], sM2r[128], sM2h[128];
    __shared__ unsigned long long sL2z[128], sL2r[128], sL2h[128];
    __shared__ unsigned long long sB2z[8], sB2r[8], sB2h[8];
    __shared__ float sP[GRU_NPB * 81];
    __shared__ float sfcW[32], sfcb[2], sprob[TT];

    int tid = threadIdx.x;
    for (int i = tid; i < 128; i += GRU_NPB) {
        int k = i >> 3, j = i & 7;
        int gi = k * 16 + 2 * j;
        sM2z[i] = pack2(g_Mz[gi], g_Mz[gi + 1]);
        sM2r[i] = pack2(g_Mr[gi], g_Mr[gi + 1]);
        sM2h[i] = pack2(g_Mh[gi], g_Mh[gi + 1]);
        sL2z[i] = pack2(Lz[256 + gi], Lz[256 + gi + 1]);
        sL2r[i] = pack2(Lr[256 + gi], Lr[256 + gi + 1]);
        sL2h[i] = pack2(Lh[256 + gi], Lh[256 + gi + 1]);
    }
    if (tid < 8) {
        sB2z[tid] = pack2(g_Bz[2 * tid], g_Bz[2 * tid + 1]);
        sB2r[tid] = pack2(g_Br[2 * tid], g_Br[2 * tid + 1]);
        sB2h[tid] = pack2(g_Bh[2 * tid], g_Bh[2 * tid + 1]);
    }
    if (tid < 32) sfcW[tid] = fcW[tid];
    if (tid < 2)  sfcb[tid] = fcb[tid];
    if (tid == 0) {
        float m = att[0];
        for (int t = 1; t < TT; t++) m = fmaxf(m, att[t]);
        float ex[TT]; float s = 0.f;
        for (int t = 0; t < TT; t++) { ex[t] = expf(att[t] - m); s += ex[t]; }
        for (int t = 0; t < TT; t++) sprob[t] = ex[t] / s;
    }
    int base = blockIdx.x * GRU_NPB;
    for (int i = tid; i < GRU_NPB * (FSTRIDE / 2); i += GRU_NPB) {
        int nd = i / (FSTRIDE / 2), c2 = i - nd * (FSTRIDE / 2);
        int g = base + nd;
        float2 f = make_float2(0.f, 0.f);
        if (g < n) {
            unsigned u = __ldg((const unsigned*)(P + (size_t)g * FSTRIDE) + c2);
            f = __half22float2(bits_h2u(u));
        }
        sP[nd * 81 + 2 * c2]     = f.x;
        sP[nd * 81 + 2 * c2 + 1] = f.y;
    }
    __syncthreads();

    int node = base + tid;
    if (node >= n) return;
    const float* myP = &sP[tid * 81];

    float H[16], Hacc[16];
#pragma unroll
    for (int h = 0; h < 16; h++) { H[h] = 0.f; Hacc[h] = 0.f; }

#pragma unroll 1
    for (int t = 0; t < TT; t++) {
        unsigned long long pk2[16], hk2[16];
#pragma unroll
        for (int k = 0; k < 16; k++) {
            float pk = myP[t * 16 + k];
            pk2[k] = pack2(pk, pk);
            hk2[k] = pack2(H[k], H[k]);
        }

        unsigned long long acc[8];
        float a[16];
        // Z gate
#pragma unroll
        for (int j = 0; j < 8; j++) acc[j] = sB2z[j];
#pragma unroll
        for (int k = 0; k < 16; k++) {
#pragma unroll
            for (int j = 0; j < 8; j++) {
                acc[j] = fma2(pk2[k], sM2z[k * 8 + j], acc[j]);
                acc[j] = fma2(hk2[k], sL2z[k * 8 + j], acc[j]);
            }
        }
        float Zg[16];
#pragma unroll
        for (int j = 0; j < 8; j++) unpack2(a[2 * j], a[2 * j + 1], acc[j]);
#pragma unroll
        for (int h = 0; h < 16; h++) Zg[h] = fast_sig(a[h]);

        // R gate
#pragma unroll
        for (int j = 0; j < 8; j++) acc[j] = sB2r[j];
#pragma unroll
        for (int k = 0; k < 16; k++) {
#pragma unroll
            for (int j = 0; j < 8; j++) {
                acc[j] = fma2(pk2[k], sM2r[k * 8 + j], acc[j]);
                acc[j] = fma2(hk2[k], sL2r[k * 8 + j], acc[j]);
            }
        }
        float Rg[16];
#pragma unroll
        for (int j = 0; j < 8; j++) unpack2(a[2 * j], a[2 * j + 1], acc[j]);
#pragma unroll
        for (int h = 0; h < 16; h++) Rg[h] = fast_sig(a[h]);

        // candidate gate: uses H*Rg
#pragma unroll
        for (int k = 0; k < 16; k++) {
            float hr = H[k] * Rg[k];
            hk2[k] = pack2(hr, hr);
        }
#pragma unroll
        for (int j = 0; j < 8; j++) acc[j] = sB2h[j];
#pragma unroll
        for (int k = 0; k < 16; k++) {
#pragma unroll
            for (int j = 0; j < 8; j++) {
                acc[j] = fma2(pk2[k], sM2h[k * 8 + j], acc[j]);
                acc[j] = fma2(hk2[k], sL2h[k * 8 + j], acc[j]);
            }
        }
#pragma unroll
        for (int j = 0; j < 8; j++) unpack2(a[2 * j], a[2 * j + 1], acc[j]);
#pragma unroll
        for (int h = 0; h < 16; h++) {
            float ht = fast_tanh(a[h]);
            H[h] = Zg[h] * H[h] + (1.f - Zg[h]) * ht;
            Hacc[h] = fmaf(sprob[t], H[h], Hacc[h]);
        }
    }

    float l0 = sfcb[0], l1 = sfcb[1];
#pragma unroll
    for (int h = 0; h < 16; h++) {
        l0 = fmaf(Hacc[h], sfcW[h * 2 + 0], l0);
        l1 = fmaf(Hacc[h], sfcW[h * 2 + 1], l1);
    }
    float m = fmaxf(l0, l1);
    float lse = m + logf(expf(l0 - m) + expf(l1 - m));
    out[(size_t)node * 2 + 0] = l0 - lse;
    out[(size_t)node * 2 + 1] = l1 - lse;
}

// ---------------- launch ----------------
extern "C" void kernel_launch(void* const* d_in, const int* in_sizes, int n_in,
                              void* d_out, int out_size) {
    const float* x   = (const float*)d_in[0];
    const int*   src = (const int*)d_in[1];
    const int*   dst = (const int*)d_in[2];
    const float* W1  = (const float*)d_in[3];
    const float* b1  = (const float*)d_in[4];
    const float* W2  = (const float*)d_in[5];
    const float* b2  = (const float*)d_in[6];
    const float* Wz  = (const float*)d_in[7];
    const float* bz  = (const float*)d_in[8];
    const float* Wr  = (const float*)d_in[9];
    const float* br  = (const float*)d_in[10];
    const float* Wh  = (const float*)d_in[11];
    const float* bh  = (const float*)d_in[12];
    const float* Lz  = (const float*)d_in[13];
    const float* lz  = (const float*)d_in[14];
    const float* Lr  = (const float*)d_in[15];
    const float* lr  = (const float*)d_in[16];
    const float* Lh  = (const float*)d_in[17];
    const float* lh  = (const float*)d_in[18];
    const float* att = (const float*)d_in[19];
    const float* fcW = (const float*)d_in[20];
    const float* fcb = (const float*)d_in[21];

    int n = in_sizes[0] / (TT * FIN);
    int e = in_sizes[1];

    void* p;
    cudaGetSymbolAddress(&p, g_cnt);     int*           cnt    = (int*)p;
    cudaGetSymbolAddress(&p, g_deg);     int*           degv   = (int*)p;
    cudaGetSymbolAddress(&p, g_row);     int*           rowp   = (int*)p;
    cudaGetSymbolAddress(&p, g_cursor);  int*           cursor = (int*)p;
    cudaGetSymbolAddress(&p, g_dis);     float*         dis    = (float*)p;
    cudaGetSymbolAddress(&p, g_dinv);    float*         dinv   = (float*)p;
    cudaGetSymbolAddress(&p, g_edge);    int2*          edge   = (int2*)p;
    cudaGetSymbolAddress(&p, g_xT);      __half*        xT     = (__half*)p;
    cudaGetSymbolAddress(&p, g_h1);      unsigned char* h1     = (unsigned char*)p;
    cudaGetSymbolAddress(&p, g_feats);   unsigned char* feats  = (unsigned char*)p;
    cudaGetSymbolAddress(&p, g_P);       __half*        P      = (__half*)p;

    int nb256_n = (n + 255) / 256;
    int nb256_e = (e + 255) / 256;
    int prep0_threads = (e > n * XREAL) ? e : n * XREAL;
    int prop_blocks = (n + 7) / 8;

    // 0: fused degree count + x transpose (fp16, 128B-aligned rows)
    kprep0<<<(prep0_threads + 255) / 256, 256>>>(dst, cnt, x, xT, n, e);
    // 1: offsets + norms
    koffsets<<<nb256_n, 256>>>(cnt, n);
    // 2: fill edge list (weights packed half2)
    kfill<<<nb256_e, 256>>>(src, dst, dis, cursor, edge, e);
    // 3: h1(fp8) = relu((S x) @ W1 + b1)      <-- profiled slot
    kprop_x<<<prop_blocks, 256>>>(xT, h1, rowp, degv, edge, dinv, W1, b1, n);
    // 4: feats(fp8) = relu((S h1) @ W2 + b2)
    kprop8<1><<<prop_blocks, 256>>>(h1, feats, rowp, degv, edge, dinv, W2, b2, n);
    // 5: P(fp16) = S feats
    kprop8<0><<<prop_blocks, 256>>>(feats, P, rowp, degv, edge, dinv, W2, b2, n);
    // 6: fold GRU gate weights
    kprepG<<<1, 256>>>(Wz, bz, Wr, br, Wh, bh, Lz, lz, Lr, lr, Lh, lh);
    // 7: GRU (FFMA2) + attention + FC + log_softmax
    kgru<<<(n + GRU_NPB - 1) / GRU_NPB, GRU_NPB>>>(P, Lz, Lr, Lh, att, fcW, fcb,
                                                   (float*)d_out, n);
}

// round 9
// speedup vs baseline: 1.1883x; 1.0410x over previous
#include <cuda_runtime.h>
#include <cuda_fp16.h>
#include <math.h>
#include <stdint.h>

// Problem constants (fixed by the dataset)
#define TT 5
#define FIN 10
#define HID 16
#define MAXN 100000
#define MAXE 3200000
#define XSTRIDE 64        // xT row stride in halves -> 128B aligned rows
#define XREAL  50
#define F8STRIDE 128      // fp8 feature row stride in BYTES (80 data + pad)
#define FSTRIDE 80        // P row stride in halves (fp16)
#define K8 16.0f          // fp8 storage scale (keeps pre-scaled values normal)

// ---------------- device scratch (static: no allocation allowed) ----------------
__device__ int    g_cnt[MAXN];         // zero at load; re-zeroed each call
__device__ int    g_deg[MAXN];
__device__ int    g_row[MAXN];
__device__ int    g_cursor[MAXN];
__device__ int    g_total;
__device__ float  g_dis[MAXN];
__device__ __align__(16) int           g_csrc[MAXE];   // src index only (weights folded away)
__device__ __align__(16) __half        g_xT[(size_t)MAXN * XSTRIDE];      // dis[s]*x[s]
__device__ __align__(16) unsigned char g_h1[(size_t)MAXN * F8STRIDE];     // K8*dis*relu(...)
__device__ __align__(16) unsigned char g_feats[(size_t)MAXN * F8STRIDE];  // K8*dis*relu(...)
__device__ __align__(16) __half        g_P[(size_t)MAXN * FSTRIDE];
__device__ float  g_Mz[256], g_Mr[256], g_Mh[256];
__device__ float  g_Bz[16],  g_Br[16],  g_Bh[16];

__device__ __forceinline__ __half2 bits_h2u(unsigned b) {
    return *reinterpret_cast<__half2*>(&b);
}
__device__ __forceinline__ float fast_tanh(float x) {
    float r;
    asm("tanh.approx.f32 %0, %1;" : "=f"(r) : "f"(x));
    return r;
}
__device__ __forceinline__ float fast_sig(float x) {
    return fmaf(0.5f, fast_tanh(0.5f * x), 0.5f);
}
// packed fp32x2 helpers (Blackwell FFMA2 — PTX-only)
__device__ __forceinline__ unsigned long long pack2(float lo, float hi) {
    unsigned long long r;
    asm("mov.b64 %0, {%1, %2};" : "=l"(r) : "f"(lo), "f"(hi));
    return r;
}
__device__ __forceinline__ void unpack2(float& lo, float& hi, unsigned long long v) {
    asm("mov.b64 {%0, %1}, %2;" : "=f"(lo), "=f"(hi) : "l"(v));
}
__device__ __forceinline__ unsigned long long fma2(unsigned long long a,
                                                   unsigned long long b,
                                                   unsigned long long c) {
    unsigned long long d;
    asm("fma.rn.f32x2 %0, %1, %2, %3;" : "=l"(d) : "l"(a), "l"(b), "l"(c));
    return d;
}
// fp8 e4m3 pack/unpack
__device__ __forceinline__ unsigned pack_e4m3x4(float a, float b, float c, float d) {
    unsigned short lo, hi;
    asm("cvt.rn.satfinite.e4m3x2.f32 %0, %1, %2;" : "=h"(lo) : "f"(b), "f"(a));
    asm("cvt.rn.satfinite.e4m3x2.f32 %0, %1, %2;" : "=h"(hi) : "f"(d), "f"(c));
    return (unsigned)lo | ((unsigned)hi << 16);
}
__device__ __forceinline__ void unpack_e4m3x4(unsigned q, __half2& p01, __half2& p23) {
    unsigned a, b;
    asm("{\n\t"
        ".reg .b16 lo, hi;\n\t"
        "mov.b32 {lo, hi}, %2;\n\t"
        "cvt.rn.f16x2.e4m3x2 %0, lo;\n\t"
        "cvt.rn.f16x2.e4m3x2 %1, hi;\n\t"
        "}" : "=r"(a), "=r"(b) : "r"(q));
    p01 = bits_h2u(a);
    p23 = bits_h2u(b);
}

// ---------------- stage 0: degree count ------------------------------------------
__global__ void kcount(const int* __restrict__ dst, int* cnt, int e) {
    int i = blockIdx.x * blockDim.x + threadIdx.x;
    if (i == 0) g_total = 0;
    if (i < e) atomicAdd(&cnt[dst[i]], 1);
}

// per-block scan + single atomic -> contiguous (unordered) slices per node
__global__ __launch_bounds__(256) void koffsets(int* cnt, int n) {
    __shared__ int sh[256];
    __shared__ int sbase;
    int tid = threadIdx.x;
    int i = blockIdx.x * 256 + tid;
    int deg = (i < n) ? cnt[i] : 0;
    sh[tid] = deg;
    __syncthreads();
    for (int off = 1; off < 256; off <<= 1) {
        int t = (tid >= off) ? sh[tid - off] : 0;
        __syncthreads();
        sh[tid] += t;
        __syncthreads();
    }
    if (tid == 255) sbase = atomicAdd(&g_total, sh[255]);
    __syncthreads();
    int start = sbase + sh[tid] - deg;
    if (i < n) {
        g_row[i]    = start;
        g_cursor[i] = start;
        g_deg[i]    = deg;
        cnt[i]      = 0;                 // restore for next replay
        g_dis[i]    = rsqrtf((float)deg + 1.0f);
    }
}

// ---------------- stage 2: fused edge fill + x transpose (pre-scaled fp16) ------
__global__ void kfill2(const int* __restrict__ src, const int* __restrict__ dst,
                       int* cursor, int* csrc,
                       const float* __restrict__ x, __half* __restrict__ xT,
                       const float* __restrict__ dis, int n, int e) {
    int i = blockIdx.x * blockDim.x + threadIdx.x;
    if (i < e) {
        int d = dst[i];
        int pos = atomicAdd(&cursor[d], 1);
        csrc[pos] = src[i];
    }
    if (i < n * XREAL) {
        int node = i / XREAL;
        int c = i - node * XREAL;
        int t = c / FIN;
        int f = c - t * FIN;
        xT[(size_t)node * XSTRIDE + c] =
            __float2half(dis[node] * x[((size_t)t * n + node) * FIN + f]);
    }
}

// ---------------- stage 3: fp16 gather-sum -> fp8 transformed output -------------
// agg[d] = dis[d] * (sum_{s in N(d)} xT[s] + xT[d])   (xT pre-scaled by dis[s])
// then out = K8*dis[d]*relu(agg @ W1 + b1) per slice, fp8.
__global__ __launch_bounds__(256) void kprop_x(const __half* __restrict__ in,
                                               unsigned char* __restrict__ out,
                                               const int* __restrict__ rowp,
                                               const int* __restrict__ degv,
                                               const int* __restrict__ csrc,
                                               const float* __restrict__ dis,
                                               const float* __restrict__ Wm,
                                               const float* __restrict__ bm, int n) {
    __shared__ float sAgg[8][52];
    __shared__ float sW[FIN * 16];
    __shared__ float sB[16];
    for (int i = threadIdx.x; i < FIN * 16; i += blockDim.x) sW[i] = Wm[i];
    if (threadIdx.x < 16) sB[threadIdx.x] = bm[threadIdx.x];
    __syncthreads();

    int wwid = threadIdx.x >> 5;
    int node = (blockIdx.x << 3) + wwid;
    if (node >= n) return;
    int lane = threadIdx.x & 31;
    int ll = (lane < 13) ? lane : 12;
    bool act = lane < 13;

    __half2 zero2 = __float2half2_rn(0.f);
    __half2 a0x = zero2, a0y = zero2, a1x = zero2, a1y = zero2;
    __half2 a2x = zero2, a2y = zero2, a3x = zero2, a3y = zero2;

    int j = rowp[node];
    int end = j + degv[node];

    // peel to 16B-aligned meta loads
    while ((j & 3) && j < end) {
        int s = __ldg(csrc + j);
        uint2 q = __ldg((const uint2*)(in + (size_t)s * XSTRIDE) + ll);
        a0x = __hadd2(a0x, bits_h2u(q.x));
        a0y = __hadd2(a0y, bits_h2u(q.y));
        j++;
    }
    for (; j + 4 <= end; j += 4) {
        int4 e4 = __ldg((const int4*)(csrc + j));
        uint2 q0 = __ldg((const uint2*)(in + (size_t)e4.x * XSTRIDE) + ll);
        uint2 q1 = __ldg((const uint2*)(in + (size_t)e4.y * XSTRIDE) + ll);
        uint2 q2 = __ldg((const uint2*)(in + (size_t)e4.z * XSTRIDE) + ll);
        uint2 q3 = __ldg((const uint2*)(in + (size_t)e4.w * XSTRIDE) + ll);
        a0x = __hadd2(a0x, bits_h2u(q0.x)); a0y = __hadd2(a0y, bits_h2u(q0.y));
        a1x = __hadd2(a1x, bits_h2u(q1.x)); a1y = __hadd2(a1y, bits_h2u(q1.y));
        a2x = __hadd2(a2x, bits_h2u(q2.x)); a2y = __hadd2(a2y, bits_h2u(q2.y));
        a3x = __hadd2(a3x, bits_h2u(q3.x)); a3y = __hadd2(a3y, bits_h2u(q3.y));
    }
    for (; j < end; j++) {
        int s = __ldg(csrc + j);
        uint2 q = __ldg((const uint2*)(in + (size_t)s * XSTRIDE) + ll);
        a0x = __hadd2(a0x, bits_h2u(q.x));
        a0y = __hadd2(a0y, bits_h2u(q.y));
    }

    // merge chains in fp32, add self row, scale by dis[node]
    float dd = __ldg(dis + node);
    uint2 sq = __ldg((const uint2*)(in + (size_t)node * XSTRIDE) + ll);
    float2 s01 = __half22float2(bits_h2u(sq.x));
    float2 s23 = __half22float2(bits_h2u(sq.y));
    float2 c0, c1, c2, c3;
    c0 = __half22float2(a0x); c1 = __half22float2(a1x);
    c2 = __half22float2(a2x); c3 = __half22float2(a3x);
    float f0 = dd * ((c0.x + c1.x) + (c2.x + c3.x) + s01.x);
    float f1 = dd * ((c0.y + c1.y) + (c2.y + c3.y) + s01.y);
    c0 = __half22float2(a0y); c1 = __half22float2(a1y);
    c2 = __half22float2(a2y); c3 = __half22float2(a3y);
    float f2 = dd * ((c0.x + c1.x) + (c2.x + c3.x) + s23.x);
    float f3 = dd * ((c0.y + c1.y) + (c2.y + c3.y) + s23.y);

    if (act) {
        float4 fv = make_float4(f0, f1, f2, f3);
        *(float4*)&sAgg[wwid][lane * 4] = fv;
    }
    __syncwarp();
    if (lane < 20) {
        float ks = K8 * dd;
        int c = lane * 4;
        int t = c >> 4;
        int h = c & 15;
        float o0 = sB[h], o1 = sB[h + 1], o2 = sB[h + 2], o3 = sB[h + 3];
#pragma unroll
        for (int f = 0; f < FIN; f++) {
            float a = sAgg[wwid][t * FIN + f];
            o0 = fmaf(a, sW[f * 16 + h],     o0);
            o1 = fmaf(a, sW[f * 16 + h + 1], o1);
            o2 = fmaf(a, sW[f * 16 + h + 2], o2);
            o3 = fmaf(a, sW[f * 16 + h + 3], o3);
        }
        unsigned pk = pack_e4m3x4(ks * fmaxf(o0, 0.f), ks * fmaxf(o1, 0.f),
                                  ks * fmaxf(o2, 0.f), ks * fmaxf(o3, 0.f));
        ((unsigned*)(out + (size_t)node * F8STRIDE))[lane] = pk;
    }
}

// ---------------- stages 4/5: fp8 gather-sum --------------------------------------
// input rows are K8*dis[s]*H[s] fp8. acc includes self row.
// MODE 1: out fp8 = K8*dis[d]*relu((dis[d]/K8 * acc) @ W2 + b2).
// MODE 0: out fp16 P = dis[d]/K8 * acc.
template <int MODE>
__global__ __launch_bounds__(256) void kprop8(const unsigned char* __restrict__ in,
                                              void* __restrict__ outv,
                                              const int* __restrict__ rowp,
                                              const int* __restrict__ degv,
                                              const int* __restrict__ csrc,
                                              const float* __restrict__ dis,
                                              const float* __restrict__ Wm,
                                              const float* __restrict__ bm, int n) {
    __shared__ float sAgg[MODE ? 8 : 1][MODE ? 80 : 4];
    __shared__ float sW[MODE ? HID * 16 : 1];
    __shared__ float sB[MODE ? 16 : 1];
    if (MODE) {
        for (int i = threadIdx.x; i < HID * 16; i += blockDim.x) sW[i] = Wm[i];
        if (threadIdx.x < 16) sB[threadIdx.x] = bm[threadIdx.x];
        __syncthreads();
    }
    int wwid = threadIdx.x >> 5;
    int node = (blockIdx.x << 3) + wwid;
    if (node >= n) return;
    int lane = threadIdx.x & 31;
    int ll = (lane < 20) ? lane : 19;
    bool act = lane < 20;

    __half2 zero2 = __float2half2_rn(0.f);
    __half2 a0x = zero2, a0y = zero2, a1x = zero2, a1y = zero2;
    __half2 a2x = zero2, a2y = zero2, a3x = zero2, a3y = zero2;

    int j = rowp[node];
    int end = j + degv[node];

    while ((j & 3) && j < end) {
        int s = __ldg(csrc + j);
        unsigned q = __ldg((const unsigned*)(in + (size_t)s * F8STRIDE) + ll);
        __half2 pa, pb;
        unpack_e4m3x4(q, pa, pb);
        a0x = __hadd2(a0x, pa);
        a0y = __hadd2(a0y, pb);
        j++;
    }
    for (; j + 4 <= end; j += 4) {
        int4 e4 = __ldg((const int4*)(csrc + j));
        unsigned q0 = __ldg((const unsigned*)(in + (size_t)e4.x * F8STRIDE) + ll);
        unsigned q1 = __ldg((const unsigned*)(in + (size_t)e4.y * F8STRIDE) + ll);
        unsigned q2 = __ldg((const unsigned*)(in + (size_t)e4.z * F8STRIDE) + ll);
        unsigned q3 = __ldg((const unsigned*)(in + (size_t)e4.w * F8STRIDE) + ll);
        __half2 pa, pb;
        unpack_e4m3x4(q0, pa, pb);
        a0x = __hadd2(a0x, pa); a0y = __hadd2(a0y, pb);
        unpack_e4m3x4(q1, pa, pb);
        a1x = __hadd2(a1x, pa); a1y = __hadd2(a1y, pb);
        unpack_e4m3x4(q2, pa, pb);
        a2x = __hadd2(a2x, pa); a2y = __hadd2(a2y, pb);
        unpack_e4m3x4(q3, pa, pb);
        a3x = __hadd2(a3x, pa); a3y = __hadd2(a3y, pb);
    }
    for (; j < end; j++) {
        int s = __ldg(csrc + j);
        unsigned q = __ldg((const unsigned*)(in + (size_t)s * F8STRIDE) + ll);
        __half2 pa, pb;
        unpack_e4m3x4(q, pa, pb);
        a0x = __hadd2(a0x, pa);
        a0y = __hadd2(a0y, pb);
    }

    // merge chains in fp32, add self row, scale by dis[node]/K8
    float dd = __ldg(dis + node);
    float sc = dd * (1.0f / K8);
    unsigned sq = __ldg((const unsigned*)(in + (size_t)node * F8STRIDE) + ll);
    __half2 sa, sb;
    unpack_e4m3x4(sq, sa, sb);
    float2 s01 = __half22float2(sa);
    float2 s23 = __half22float2(sb);
    float2 c0, c1, c2, c3;
    c0 = __half22float2(a0x); c1 = __half22float2(a1x);
    c2 = __half22float2(a2x); c3 = __half22float2(a3x);
    float f0 = sc * ((c0.x + c1.x) + (c2.x + c3.x) + s01.x);
    float f1 = sc * ((c0.y + c1.y) + (c2.y + c3.y) + s01.y);
    c0 = __half22float2(a0y); c1 = __half22float2(a1y);
    c2 = __half22float2(a2y); c3 = __half22float2(a3y);
    float f2 = sc * ((c0.x + c1.x) + (c2.x + c3.x) + s23.x);
    float f3 = sc * ((c0.y + c1.y) + (c2.y + c3.y) + s23.y);

    if (!MODE) {
        if (act) {
            __half2 o01 = __floats2half2_rn(f0, f1);
            __half2 o23 = __floats2half2_rn(f2, f3);
            uint2 pk;
            pk.x = *reinterpret_cast<unsigned*>(&o01);
            pk.y = *reinterpret_cast<unsigned*>(&o23);
            *((uint2*)((__half*)outv + (size_t)node * FSTRIDE) + lane) = pk;
        }
        return;
    }

    if (act) {
        float4 fv = make_float4(f0, f1, f2, f3);
        *(float4*)&sAgg[wwid][lane * 4] = fv;
    }
    __syncwarp();
    if (lane < 20) {
        float ks = K8 * dd;
        int c = lane * 4;
        int t = c >> 4;
        int h = c & 15;
        float o0 = sB[h], o1 = sB[h + 1], o2 = sB[h + 2], o3 = sB[h + 3];
#pragma unroll
        for (int f = 0; f < HID; f++) {
            float a = sAgg[wwid][t * HID + f];
            o0 = fmaf(a, sW[f * 16 + h],     o0);
            o1 = fmaf(a, sW[f * 16 + h + 1], o1);
            o2 = fmaf(a, sW[f * 16 + h + 2], o2);
            o3 = fmaf(a, sW[f * 16 + h + 3], o3);
        }
        unsigned pk = pack_e4m3x4(ks * fmaxf(o0, 0.f), ks * fmaxf(o1, 0.f),
                                  ks * fmaxf(o2, 0.f), ks * fmaxf(o3, 0.f));
        ((unsigned*)((unsigned char*)outv + (size_t)node * F8STRIDE))[lane] = pk;
    }
}

// ---------------- fold gate matmuls: M* = W* @ L*[0:16], B* = b*@L*[0:16] + l* ----
__global__ void kprepG(const float* Wz, const float* bz, const float* Wr, const float* br,
                       const float* Wh, const float* bh,
                       const float* Lz, const float* lz, const float* Lr, const float* lr,
                       const float* Lh, const float* lh) {
    int tid = threadIdx.x;  // 256
    int k = tid >> 4, h = tid & 15;
    float mz = 0.f, mr = 0.f, mh = 0.f;
#pragma unroll
    for (int j = 0; j < 16; j++) {
        mz = fmaf(Wz[k * 16 + j], Lz[j * 16 + h], mz);
        mr = fmaf(Wr[k * 16 + j], Lr[j * 16 + h], mr);
        mh = fmaf(Wh[k * 16 + j], Lh[j * 16 + h], mh);
    }
    g_Mz[tid] = mz; g_Mr[tid] = mr; g_Mh[tid] = mh;
    if (tid < 16) {
        float az = lz[tid], ar = lr[tid], ah = lh[tid];
#pragma unroll
        for (int j = 0; j < 16; j++) {
            az = fmaf(bz[j], Lz[j * 16 + tid], az);
            ar = fmaf(br[j], Lr[j * 16 + tid], ar);
            ah = fmaf(bh[j], Lh[j * 16 + tid], ah);
        }
        g_Bz[tid] = az; g_Br[tid] = ar; g_Bh[tid] = ah;
    }
}

// ---------------- GRU (packed f32x2 FFMA2) + attention + FC + log_softmax -------
#define GRU_NPB 96
__global__ __launch_bounds__(GRU_NPB) void kgru(const __half* __restrict__ P,
                                                const float* __restrict__ Lz,
                                                const float* __restrict__ Lr,
                                                const float* __restrict__ Lh,
                                                const float* __restrict__ att,
                                                const float* __restrict__ fcW,
                                                const float* __restrict__ fcb,
                                                float* __restrict__ out, int n) {
    __shared__ unsigned long long sM2z[128], sM2r[128], sM2h[128];
    __shared__ unsigned long long sL2z[128], sL2r[128], sL2h[128];
    __shared__ unsigned long long sB2z[8], sB2r[8], sB2h[8];
    __shared__ float sP[GRU_NPB * 81];
    __shared__ float sfcW[32], sfcb[2], sprob[TT];

    int tid = threadIdx.x;
    for (int i = tid; i < 128; i += GRU_NPB) {
        int k = i >> 3, j = i & 7;
        int gi = k * 16 + 2 * j;
        sM2z[i] = pack2(g_Mz[gi], g_Mz[gi + 1]);
        sM2r[i] = pack2(g_Mr[gi], g_Mr[gi + 1]);
        sM2h[i] = pack2(g_Mh[gi], g_Mh[gi + 1]);
        sL2z[i] = pack2(Lz[256 + gi], Lz[256 + gi + 1]);
        sL2r[i] = pack2(Lr[256 + gi], Lr[256 + gi + 1]);
        sL2h[i] = pack2(Lh[256 + gi], Lh[256 + gi + 1]);
    }
    if (tid < 8) {
        sB2z[tid] = pack2(g_Bz[2 * tid], g_Bz[2 * tid + 1]);
        sB2r[tid] = pack2(g_Br[2 * tid], g_Br[2 * tid + 1]);
        sB2h[tid] = pack2(g_Bh[2 * tid], g_Bh[2 * tid + 1]);
    }
    if (tid < 32) sfcW[tid] = fcW[tid];
    if (tid < 2)  sfcb[tid] = fcb[tid];
    if (tid == 0) {
        float m = att[0];
        for (int t = 1; t < TT; t++) m = fmaxf(m, att[t]);
        float ex[TT]; float s = 0.f;
        for (int t = 0; t < TT; t++) { ex[t] = expf(att[t] - m); s += ex[t]; }
        for (int t = 0; t < TT; t++) sprob[t] = ex[t] / s;
    }
    int base = blockIdx.x * GRU_NPB;
    for (int i = tid; i < GRU_NPB * (FSTRIDE / 2); i += GRU_NPB) {
        int nd = i / (FSTRIDE / 2), c2 = i - nd * (FSTRIDE / 2);
        int g = base + nd;
        float2 f = make_float2(0.f, 0.f);
        if (g < n) {
            unsigned u = __ldg((const unsigned*)(P + (size_t)g * FSTRIDE) + c2);
            f = __half22float2(bits_h2u(u));
        }
        sP[nd * 81 + 2 * c2]     = f.x;
        sP[nd * 81 + 2 * c2 + 1] = f.y;
    }
    __syncthreads();

    int node = base + tid;
    if (node >= n) return;
    const float* myP = &sP[tid * 81];

    float H[16], Hacc[16];
#pragma unroll
    for (int h = 0; h < 16; h++) { H[h] = 0.f; Hacc[h] = 0.f; }

#pragma unroll 1
    for (int t = 0; t < TT; t++) {
        unsigned long long pk2[16], hk2[16];
#pragma unroll
        for (int k = 0; k < 16; k++) {
            float pk = myP[t * 16 + k];
            pk2[k] = pack2(pk, pk);
            hk2[k] = pack2(H[k], H[k]);
        }

        unsigned long long acc[8];
        float a[16];
        // Z gate
#pragma unroll
        for (int j = 0; j < 8; j++) acc[j] = sB2z[j];
#pragma unroll
        for (int k = 0; k < 16; k++) {
#pragma unroll
            for (int j = 0; j < 8; j++) {
                acc[j] = fma2(pk2[k], sM2z[k * 8 + j], acc[j]);
                acc[j] = fma2(hk2[k], sL2z[k * 8 + j], acc[j]);
            }
        }
        float Zg[16];
#pragma unroll
        for (int j = 0; j < 8; j++) unpack2(a[2 * j], a[2 * j + 1], acc[j]);
#pragma unroll
        for (int h = 0; h < 16; h++) Zg[h] = fast_sig(a[h]);

        // R gate
#pragma unroll
        for (int j = 0; j < 8; j++) acc[j] = sB2r[j];
#pragma unroll
        for (int k = 0; k < 16; k++) {
#pragma unroll
            for (int j = 0; j < 8; j++) {
                acc[j] = fma2(pk2[k], sM2r[k * 8 + j], acc[j]);
                acc[j] = fma2(hk2[k], sL2r[k * 8 + j], acc[j]);
            }
        }
        float Rg[16];
#pragma unroll
        for (int j = 0; j < 8; j++) unpack2(a[2 * j], a[2 * j + 1], acc[j]);
#pragma unroll
        for (int h = 0; h < 16; h++) Rg[h] = fast_sig(a[h]);

        // candidate gate: uses H*Rg
#pragma unroll
        for (int k = 0; k < 16; k++) {
            float hr = H[k] * Rg[k];
            hk2[k] = pack2(hr, hr);
        }
#pragma unroll
        for (int j = 0; j < 8; j++) acc[j] = sB2h[j];
#pragma unroll
        for (int k = 0; k < 16; k++) {
#pragma unroll
            for (int j = 0; j < 8; j++) {
                acc[j] = fma2(pk2[k], sM2h[k * 8 + j], acc[j]);
                acc[j] = fma2(hk2[k], sL2h[k * 8 + j], acc[j]);
            }
        }
#pragma unroll
        for (int j = 0; j < 8; j++) unpack2(a[2 * j], a[2 * j + 1], acc[j]);
#pragma unroll
        for (int h = 0; h < 16; h++) {
            float ht = fast_tanh(a[h]);
            H[h] = Zg[h] * H[h] + (1.f - Zg[h]) * ht;
            Hacc[h] = fmaf(sprob[t], H[h], Hacc[h]);
        }
    }

    float l0 = sfcb[0], l1 = sfcb[1];
#pragma unroll
    for (int h = 0; h < 16; h++) {
        l0 = fmaf(Hacc[h], sfcW[h * 2 + 0], l0);
        l1 = fmaf(Hacc[h], sfcW[h * 2 + 1], l1);
    }
    float m = fmaxf(l0, l1);
    float lse = m + logf(expf(l0 - m) + expf(l1 - m));
    out[(size_t)node * 2 + 0] = l0 - lse;
    out[(size_t)node * 2 + 1] = l1 - lse;
}

// ---------------- launch ----------------
extern "C" void kernel_launch(void* const* d_in, const int* in_sizes, int n_in,
                              void* d_out, int out_size) {
    const float* x   = (const float*)d_in[0];
    const int*   src = (const int*)d_in[1];
    const int*   dst = (const int*)d_in[2];
    const float* W1  = (const float*)d_in[3];
    const float* b1  = (const float*)d_in[4];
    const float* W2  = (const float*)d_in[5];
    const float* b2  = (const float*)d_in[6];
    const float* Wz  = (const float*)d_in[7];
    const float* bz  = (const float*)d_in[8];
    const float* Wr  = (const float*)d_in[9];
    const float* br  = (const float*)d_in[10];
    const float* Wh  = (const float*)d_in[11];
    const float* bh  = (const float*)d_in[12];
    const float* Lz  = (const float*)d_in[13];
    const float* lz  = (const float*)d_in[14];
    const float* Lr  = (const float*)d_in[15];
    const float* lr  = (const float*)d_in[16];
    const float* Lh  = (const float*)d_in[17];
    const float* lh  = (const float*)d_in[18];
    const float* att = (const float*)d_in[19];
    const float* fcW = (const float*)d_in[20];
    const float* fcb = (const float*)d_in[21];

    int n = in_sizes[0] / (TT * FIN);
    int e = in_sizes[1];

    void* p;
    cudaGetSymbolAddress(&p, g_cnt);     int*           cnt    = (int*)p;
    cudaGetSymbolAddress(&p, g_deg);     int*           degv   = (int*)p;
    cudaGetSymbolAddress(&p, g_row);     int*           rowp   = (int*)p;
    cudaGetSymbolAddress(&p, g_cursor);  int*           cursor = (int*)p;
    cudaGetSymbolAddress(&p, g_dis);     float*         dis    = (float*)p;
    cudaGetSymbolAddress(&p, g_csrc);    int*           csrc   = (int*)p;
    cudaGetSymbolAddress(&p, g_xT);      __half*        xT     = (__half*)p;
    cudaGetSymbolAddress(&p, g_h1);      unsigned char* h1     = (unsigned char*)p;
    cudaGetSymbolAddress(&p, g_feats);   unsigned char* feats  = (unsigned char*)p;
    cudaGetSymbolAddress(&p, g_P);       __half*        P      = (__half*)p;

    int nb256_n = (n + 255) / 256;
    int nb256_e = (e + 255) / 256;
    int fill_threads = (e > n * XREAL) ? e : n * XREAL;
    int prop_blocks = (n + 7) / 8;

    // 0: degree count
    kcount<<<nb256_e, 256>>>(dst, cnt, e);
    // 1: offsets + dis
    koffsets<<<nb256_n, 256>>>(cnt, n);
    // 2: fused edge fill (src only) + x transpose pre-scaled by dis
    kfill2<<<(fill_threads + 255) / 256, 256>>>(src, dst, cursor, csrc, x, xT, dis, n, e);
    // 3: h1(fp8) = K8*dis*relu((S x) @ W1 + b1)   <-- profiled slot
    kprop_x<<<prop_blocks, 256>>>(xT, h1, rowp, degv, csrc, dis, W1, b1, n);
    // 4: feats(fp8) = K8*dis*relu((S h1) @ W2 + b2)
    kprop8<1><<<prop_blocks, 256>>>(h1, feats, rowp, degv, csrc, dis, W2, b2, n);
    // 5: P(fp16) = S feats
    kprop8<0><<<prop_blocks, 256>>>(feats, P, rowp, degv, csrc, dis, W2, b2, n);
    // 6: fold GRU gate weights
    kprepG<<<1, 256>>>(Wz, bz, Wr, br, Wh, bh, Lz, lz, Lr, lr, Lh, lh);
    // 7: GRU (FFMA2) + attention + FC + log_softmax
    kgru<<<(n + GRU_NPB - 1) / GRU_NPB, GRU_NPB>>>(P, Lz, Lr, Lh, att, fcW, fcb,
                                                   (float*)d_out, n);
}

// round 10
// speedup vs baseline: 1.1956x; 1.0061x over previous
#include <cuda_runtime.h>
#include <cuda_fp16.h>
#include <math.h>
#include <stdint.h>

// Problem constants (fixed by the dataset)
#define TT 5
#define FIN 10
#define HID 16
#define MAXN 100000
#define MAXE 3200000
#define XSTRIDE 64        // xT row stride in halves -> 128B aligned rows
#define XREAL  50
#define F8STRIDE 128      // fp8 feature row stride in BYTES (80 data + pad)
#define FSTRIDE 80        // P row stride in halves (fp16)
#define K8 16.0f          // fp8 storage scale (keeps pre-scaled values normal)

// ---------------- device scratch (static: no allocation allowed) ----------------
__device__ int    g_cnt[MAXN];         // zero at load; re-zeroed each call
__device__ int    g_deg[MAXN];
__device__ int    g_row[MAXN];
__device__ int    g_cursor[MAXN];
__device__ int    g_total;
__device__ float  g_dis[MAXN];
__device__ __align__(16) int           g_csrc[MAXE];   // src index only (weights folded away)
__device__ __align__(16) __half        g_xT[(size_t)MAXN * XSTRIDE];      // dis[s]*x[s]
__device__ __align__(16) unsigned char g_h1[(size_t)MAXN * F8STRIDE];     // K8*dis*relu(...)
__device__ __align__(16) unsigned char g_feats[(size_t)MAXN * F8STRIDE];  // K8*dis*relu(...)
__device__ __align__(16) __half        g_P[(size_t)MAXN * FSTRIDE];
__device__ float  g_Mz[256], g_Mr[256], g_Mh[256];
__device__ float  g_Bz[16],  g_Br[16],  g_Bh[16];

__device__ __forceinline__ __half2 bits_h2u(unsigned b) {
    return *reinterpret_cast<__half2*>(&b);
}
__device__ __forceinline__ float fast_tanh(float x) {
    float r;
    asm("tanh.approx.f32 %0, %1;" : "=f"(r) : "f"(x));
    return r;
}
__device__ __forceinline__ float fast_sig(float x) {
    return fmaf(0.5f, fast_tanh(0.5f * x), 0.5f);
}
// packed fp32x2 helpers (Blackwell FFMA2 — PTX-only)
__device__ __forceinline__ unsigned long long pack2(float lo, float hi) {
    unsigned long long r;
    asm("mov.b64 %0, {%1, %2};" : "=l"(r) : "f"(lo), "f"(hi));
    return r;
}
__device__ __forceinline__ void unpack2(float& lo, float& hi, unsigned long long v) {
    asm("mov.b64 {%0, %1}, %2;" : "=f"(lo), "=f"(hi) : "l"(v));
}
__device__ __forceinline__ unsigned long long fma2(unsigned long long a,
                                                   unsigned long long b,
                                                   unsigned long long c) {
    unsigned long long d;
    asm("fma.rn.f32x2 %0, %1, %2, %3;" : "=l"(d) : "l"(a), "l"(b), "l"(c));
    return d;
}
// fp8 e4m3 pack/unpack
__device__ __forceinline__ unsigned pack_e4m3x4(float a, float b, float c, float d) {
    unsigned short lo, hi;
    asm("cvt.rn.satfinite.e4m3x2.f32 %0, %1, %2;" : "=h"(lo) : "f"(b), "f"(a));
    asm("cvt.rn.satfinite.e4m3x2.f32 %0, %1, %2;" : "=h"(hi) : "f"(d), "f"(c));
    return (unsigned)lo | ((unsigned)hi << 16);
}
__device__ __forceinline__ void unpack_e4m3x4(unsigned q, __half2& p01, __half2& p23) {
    unsigned a, b;
    asm("{\n\t"
        ".reg .b16 lo, hi;\n\t"
        "mov.b32 {lo, hi}, %2;\n\t"
        "cvt.rn.f16x2.e4m3x2 %0, lo;\n\t"
        "cvt.rn.f16x2.e4m3x2 %1, hi;\n\t"
        "}" : "=r"(a), "=r"(b) : "r"(q));
    p01 = bits_h2u(a);
    p23 = bits_h2u(b);
}

// ---------------- stage 0: degree count ------------------------------------------
__global__ void kcount(const int* __restrict__ dst, int* cnt, int e) {
    int i = blockIdx.x * blockDim.x + threadIdx.x;
    if (i == 0) g_total = 0;
    if (i < e) atomicAdd(&cnt[dst[i]], 1);
}

// per-block scan + single atomic -> contiguous (unordered) slices per node
__global__ __launch_bounds__(256) void koffsets(int* cnt, int n) {
    __shared__ int sh[256];
    __shared__ int sbase;
    int tid = threadIdx.x;
    int i = blockIdx.x * 256 + tid;
    int deg = (i < n) ? cnt[i] : 0;
    sh[tid] = deg;
    __syncthreads();
    for (int off = 1; off < 256; off <<= 1) {
        int t = (tid >= off) ? sh[tid - off] : 0;
        __syncthreads();
        sh[tid] += t;
        __syncthreads();
    }
    if (tid == 255) sbase = atomicAdd(&g_total, sh[255]);
    __syncthreads();
    int start = sbase + sh[tid] - deg;
    if (i < n) {
        g_row[i]    = start;
        g_cursor[i] = start;
        g_deg[i]    = deg;
        cnt[i]      = 0;                 // restore for next replay
        g_dis[i]    = rsqrtf((float)deg + 1.0f);
    }
}

// ---------------- stage 2: fused edge fill + x transpose (pre-scaled fp16) ------
__global__ void kfill2(const int* __restrict__ src, const int* __restrict__ dst,
                       int* cursor, int* csrc,
                       const float* __restrict__ x, __half* __restrict__ xT,
                       const float* __restrict__ dis, int n, int e) {
    int i = blockIdx.x * blockDim.x + threadIdx.x;
    if (i < e) {
        int d = dst[i];
        int pos = atomicAdd(&cursor[d], 1);
        csrc[pos] = src[i];
    }
    if (i < n * XREAL) {
        int node = i / XREAL;
        int c = i - node * XREAL;
        int t = c / FIN;
        int f = c - t * FIN;
        xT[(size_t)node * XSTRIDE + c] =
            __float2half(dis[node] * x[((size_t)t * n + node) * FIN + f]);
    }
}

// ---------------- stage 3: fp16 gather-sum -> fp8 transformed output -------------
// agg[d] = dis[d] * (sum_{s in N(d)} xT[s] + xT[d])   (xT pre-scaled by dis[s])
// then out = K8*dis[d]*relu(agg @ W1 + b1) per slice, fp8.
__global__ __launch_bounds__(256, 8) void kprop_x(const __half* __restrict__ in,
                                                  unsigned char* __restrict__ out,
                                                  const int* __restrict__ rowp,
                                                  const int* __restrict__ degv,
                                                  const int* __restrict__ csrc,
                                                  const float* __restrict__ dis,
                                                  const float* __restrict__ Wm,
                                                  const float* __restrict__ bm, int n) {
    __shared__ float sAgg[8][52];
    __shared__ float sW[FIN * 16];
    __shared__ float sB[16];
    for (int i = threadIdx.x; i < FIN * 16; i += blockDim.x) sW[i] = Wm[i];
    if (threadIdx.x < 16) sB[threadIdx.x] = bm[threadIdx.x];
    __syncthreads();

    int wwid = threadIdx.x >> 5;
    int node = (blockIdx.x << 3) + wwid;
    if (node >= n) return;
    int lane = threadIdx.x & 31;
    int ll = (lane < 13) ? lane : 12;
    bool act = lane < 13;

    __half2 zero2 = __float2half2_rn(0.f);
    __half2 a0x = zero2, a0y = zero2, a1x = zero2, a1y = zero2;
    __half2 a2x = zero2, a2y = zero2, a3x = zero2, a3y = zero2;

    int j = rowp[node];
    int end = j + degv[node];

    // peel to 16B-aligned meta loads
    while ((j & 3) && j < end) {
        int s = __ldg(csrc + j);
        uint2 q = __ldg((const uint2*)(in + (size_t)s * XSTRIDE) + ll);
        a0x = __hadd2(a0x, bits_h2u(q.x));
        a0y = __hadd2(a0y, bits_h2u(q.y));
        j++;
    }
    for (; j + 4 <= end; j += 4) {
        int4 e4 = __ldg((const int4*)(csrc + j));
        uint2 q0 = __ldg((const uint2*)(in + (size_t)e4.x * XSTRIDE) + ll);
        uint2 q1 = __ldg((const uint2*)(in + (size_t)e4.y * XSTRIDE) + ll);
        uint2 q2 = __ldg((const uint2*)(in + (size_t)e4.z * XSTRIDE) + ll);
        uint2 q3 = __ldg((const uint2*)(in + (size_t)e4.w * XSTRIDE) + ll);
        a0x = __hadd2(a0x, bits_h2u(q0.x)); a0y = __hadd2(a0y, bits_h2u(q0.y));
        a1x = __hadd2(a1x, bits_h2u(q1.x)); a1y = __hadd2(a1y, bits_h2u(q1.y));
        a2x = __hadd2(a2x, bits_h2u(q2.x)); a2y = __hadd2(a2y, bits_h2u(q2.y));
        a3x = __hadd2(a3x, bits_h2u(q3.x)); a3y = __hadd2(a3y, bits_h2u(q3.y));
    }
    for (; j < end; j++) {
        int s = __ldg(csrc + j);
        uint2 q = __ldg((const uint2*)(in + (size_t)s * XSTRIDE) + ll);
        a0x = __hadd2(a0x, bits_h2u(q.x));
        a0y = __hadd2(a0y, bits_h2u(q.y));
    }

    // merge chains in fp32, add self row, scale by dis[node]
    float dd = __ldg(dis + node);
    uint2 sq = __ldg((const uint2*)(in + (size_t)node * XSTRIDE) + ll);
    float2 s01 = __half22float2(bits_h2u(sq.x));
    float2 s23 = __half22float2(bits_h2u(sq.y));
    float2 c0, c1, c2, c3;
    c0 = __half22float2(a0x); c1 = __half22float2(a1x);
    c2 = __half22float2(a2x); c3 = __half22float2(a3x);
    float f0 = dd * ((c0.x + c1.x) + (c2.x + c3.x) + s01.x);
    float f1 = dd * ((c0.y + c1.y) + (c2.y + c3.y) + s01.y);
    c0 = __half22float2(a0y); c1 = __half22float2(a1y);
    c2 = __half22float2(a2y); c3 = __half22float2(a3y);
    float f2 = dd * ((c0.x + c1.x) + (c2.x + c3.x) + s23.x);
    float f3 = dd * ((c0.y + c1.y) + (c2.y + c3.y) + s23.y);

    if (act) {
        float4 fv = make_float4(f0, f1, f2, f3);
        *(float4*)&sAgg[wwid][lane * 4] = fv;
    }
    __syncwarp();
    if (lane < 20) {
        float ks = K8 * dd;
        int c = lane * 4;
        int t = c >> 4;
        int h = c & 15;
        float o0 = sB[h], o1 = sB[h + 1], o2 = sB[h + 2], o3 = sB[h + 3];
#pragma unroll
        for (int f = 0; f < FIN; f++) {
            float a = sAgg[wwid][t * FIN + f];
            o0 = fmaf(a, sW[f * 16 + h],     o0);
            o1 = fmaf(a, sW[f * 16 + h + 1], o1);
            o2 = fmaf(a, sW[f * 16 + h + 2], o2);
            o3 = fmaf(a, sW[f * 16 + h + 3], o3);
        }
        unsigned pk = pack_e4m3x4(ks * fmaxf(o0, 0.f), ks * fmaxf(o1, 0.f),
                                  ks * fmaxf(o2, 0.f), ks * fmaxf(o3, 0.f));
        ((unsigned*)(out + (size_t)node * F8STRIDE))[lane] = pk;
    }
}

// ---------------- stages 4/5: fp8 gather-sum --------------------------------------
// input rows are K8*dis[s]*H[s] fp8. acc includes self row.
// MODE 1: out fp8 = K8*dis[d]*relu((dis[d]/K8 * acc) @ W2 + b2).
// MODE 0: out fp16 P = dis[d]/K8 * acc.
template <int MODE>
__global__ __launch_bounds__(256, 8) void kprop8(const unsigned char* __restrict__ in,
                                                 void* __restrict__ outv,
                                                 const int* __restrict__ rowp,
                                                 const int* __restrict__ degv,
                                                 const int* __restrict__ csrc,
                                                 const float* __restrict__ dis,
                                                 const float* __restrict__ Wm,
                                                 const float* __restrict__ bm, int n) {
    __shared__ float sAgg[MODE ? 8 : 1][MODE ? 80 : 4];
    __shared__ float sW[MODE ? HID * 16 : 1];
    __shared__ float sB[MODE ? 16 : 1];
    if (MODE) {
        for (int i = threadIdx.x; i < HID * 16; i += blockDim.x) sW[i] = Wm[i];
        if (threadIdx.x < 16) sB[threadIdx.x] = bm[threadIdx.x];
        __syncthreads();
    }
    int wwid = threadIdx.x >> 5;
    int node = (blockIdx.x << 3) + wwid;
    if (node >= n) return;
    int lane = threadIdx.x & 31;
    int ll = (lane < 20) ? lane : 19;
    bool act = lane < 20;

    __half2 zero2 = __float2half2_rn(0.f);
    __half2 a0x = zero2, a0y = zero2, a1x = zero2, a1y = zero2;
    __half2 a2x = zero2, a2y = zero2, a3x = zero2, a3y = zero2;

    int j = rowp[node];
    int end = j + degv[node];

    while ((j & 3) && j < end) {
        int s = __ldg(csrc + j);
        unsigned q = __ldg((const unsigned*)(in + (size_t)s * F8STRIDE) + ll);
        __half2 pa, pb;
        unpack_e4m3x4(q, pa, pb);
        a0x = __hadd2(a0x, pa);
        a0y = __hadd2(a0y, pb);
        j++;
    }
    for (; j + 4 <= end; j += 4) {
        int4 e4 = __ldg((const int4*)(csrc + j));
        unsigned q0 = __ldg((const unsigned*)(in + (size_t)e4.x * F8STRIDE) + ll);
        unsigned q1 = __ldg((const unsigned*)(in + (size_t)e4.y * F8STRIDE) + ll);
        unsigned q2 = __ldg((const unsigned*)(in + (size_t)e4.z * F8STRIDE) + ll);
        unsigned q3 = __ldg((const unsigned*)(in + (size_t)e4.w * F8STRIDE) + ll);
        __half2 pa, pb;
        unpack_e4m3x4(q0, pa, pb);
        a0x = __hadd2(a0x, pa); a0y = __hadd2(a0y, pb);
        unpack_e4m3x4(q1, pa, pb);
        a1x = __hadd2(a1x, pa); a1y = __hadd2(a1y, pb);
        unpack_e4m3x4(q2, pa, pb);
        a2x = __hadd2(a2x, pa); a2y = __hadd2(a2y, pb);
        unpack_e4m3x4(q3, pa, pb);
        a3x = __hadd2(a3x, pa); a3y = __hadd2(a3y, pb);
    }
    for (; j < end; j++) {
        int s = __ldg(csrc + j);
        unsigned q = __ldg((const unsigned*)(in + (size_t)s * F8STRIDE) + ll);
        __half2 pa, pb;
        unpack_e4m3x4(q, pa, pb);
        a0x = __hadd2(a0x, pa);
        a0y = __hadd2(a0y, pb);
    }

    // merge chains in fp32, add self row, scale by dis[node]/K8
    float dd = __ldg(dis + node);
    float sc = dd * (1.0f / K8);
    unsigned sq = __ldg((const unsigned*)(in + (size_t)node * F8STRIDE) + ll);
    __half2 sa, sb;
    unpack_e4m3x4(sq, sa, sb);
    float2 s01 = __half22float2(sa);
    float2 s23 = __half22float2(sb);
    float2 c0, c1, c2, c3;
    c0 = __half22float2(a0x); c1 = __half22float2(a1x);
    c2 = __half22float2(a2x); c3 = __half22float2(a3x);
    float f0 = sc * ((c0.x + c1.x) + (c2.x + c3.x) + s01.x);
    float f1 = sc * ((c0.y + c1.y) + (c2.y + c3.y) + s01.y);
    c0 = __half22float2(a0y); c1 = __half22float2(a1y);
    c2 = __half22float2(a2y); c3 = __half22float2(a3y);
    float f2 = sc * ((c0.x + c1.x) + (c2.x + c3.x) + s23.x);
    float f3 = sc * ((c0.y + c1.y) + (c2.y + c3.y) + s23.y);

    if (!MODE) {
        if (act) {
            __half2 o01 = __floats2half2_rn(f0, f1);
            __half2 o23 = __floats2half2_rn(f2, f3);
            uint2 pk;
            pk.x = *reinterpret_cast<unsigned*>(&o01);
            pk.y = *reinterpret_cast<unsigned*>(&o23);
            *((uint2*)((__half*)outv + (size_t)node * FSTRIDE) + lane) = pk;
        }
        return;
    }

    if (act) {
        float4 fv = make_float4(f0, f1, f2, f3);
        *(float4*)&sAgg[wwid][lane * 4] = fv;
    }
    __syncwarp();
    if (lane < 20) {
        float ks = K8 * dd;
        int c = lane * 4;
        int t = c >> 4;
        int h = c & 15;
        float o0 = sB[h], o1 = sB[h + 1], o2 = sB[h + 2], o3 = sB[h + 3];
#pragma unroll
        for (int f = 0; f < HID; f++) {
            float a = sAgg[wwid][t * HID + f];
            o0 = fmaf(a, sW[f * 16 + h],     o0);
            o1 = fmaf(a, sW[f * 16 + h + 1], o1);
            o2 = fmaf(a, sW[f * 16 + h + 2], o2);
            o3 = fmaf(a, sW[f * 16 + h + 3], o3);
        }
        unsigned pk = pack_e4m3x4(ks * fmaxf(o0, 0.f), ks * fmaxf(o1, 0.f),
                                  ks * fmaxf(o2, 0.f), ks * fmaxf(o3, 0.f));
        ((unsigned*)((unsigned char*)outv + (size_t)node * F8STRIDE))[lane] = pk;
    }
}

// ---------------- fold gate matmuls: M* = W* @ L*[0:16], B* = b*@L*[0:16] + l* ----
__global__ void kprepG(const float* Wz, const float* bz, const float* Wr, const float* br,
                       const float* Wh, const float* bh,
                       const float* Lz, const float* lz, const float* Lr, const float* lr,
                       const float* Lh, const float* lh) {
    int tid = threadIdx.x;  // 256
    int k = tid >> 4, h = tid & 15;
    float mz = 0.f, mr = 0.f, mh = 0.f;
#pragma unroll
    for (int j = 0; j < 16; j++) {
        mz = fmaf(Wz[k * 16 + j], Lz[j * 16 + h], mz);
        mr = fmaf(Wr[k * 16 + j], Lr[j * 16 + h], mr);
        mh = fmaf(Wh[k * 16 + j], Lh[j * 16 + h], mh);
    }
    g_Mz[tid] = mz; g_Mr[tid] = mr; g_Mh[tid] = mh;
    if (tid < 16) {
        float az = lz[tid], ar = lr[tid], ah = lh[tid];
#pragma unroll
        for (int j = 0; j < 16; j++) {
            az = fmaf(bz[j], Lz[j * 16 + tid], az);
            ar = fmaf(br[j], Lr[j * 16 + tid], ar);
            ah = fmaf(bh[j], Lh[j * 16 + tid], ah);
        }
        g_Bz[tid] = az; g_Br[tid] = ar; g_Bh[tid] = ah;
    }
}

// ---------------- GRU (packed f32x2 FFMA2) + attention + FC + log_softmax -------
#define GRU_NPB 96
__global__ __launch_bounds__(GRU_NPB) void kgru(const __half* __restrict__ P,
                                                const float* __restrict__ Lz,
                                                const float* __restrict__ Lr,
                                                const float* __restrict__ Lh,
                                                const float* __restrict__ att,
                                                const float* __restrict__ fcW,
                                                const float* __restrict__ fcb,
                                                float* __restrict__ out, int n) {
    __shared__ unsigned long long sM2z[128], sM2r[128], sM2h[128];
    __shared__ unsigned long long sL2z[128], sL2r[128], sL2h[128];
    __shared__ unsigned long long sB2z[8], sB2r[8], sB2h[8];
    __shared__ float sP[GRU_NPB * 81];
    __shared__ float sfcW[32], sfcb[2], sprob[TT];

    int tid = threadIdx.x;
    for (int i = tid; i < 128; i += GRU_NPB) {
        int k = i >> 3, j = i & 7;
        int gi = k * 16 + 2 * j;
        sM2z[i] = pack2(g_Mz[gi], g_Mz[gi + 1]);
        sM2r[i] = pack2(g_Mr[gi], g_Mr[gi + 1]);
        sM2h[i] = pack2(g_Mh[gi], g_Mh[gi + 1]);
        sL2z[i] = pack2(Lz[256 + gi], Lz[256 + gi + 1]);
        sL2r[i] = pack2(Lr[256 + gi], Lr[256 + gi + 1]);
        sL2h[i] = pack2(Lh[256 + gi], Lh[256 + gi + 1]);
    }
    if (tid < 8) {
        sB2z[tid] = pack2(g_Bz[2 * tid], g_Bz[2 * tid + 1]);
        sB2r[tid] = pack2(g_Br[2 * tid], g_Br[2 * tid + 1]);
        sB2h[tid] = pack2(g_Bh[2 * tid], g_Bh[2 * tid + 1]);
    }
    if (tid < 32) sfcW[tid] = fcW[tid];
    if (tid < 2)  sfcb[tid] = fcb[tid];
    if (tid == 0) {
        float m = att[0];
        for (int t = 1; t < TT; t++) m = fmaxf(m, att[t]);
        float ex[TT]; float s = 0.f;
        for (int t = 0; t < TT; t++) { ex[t] = expf(att[t] - m); s += ex[t]; }
        for (int t = 0; t < TT; t++) sprob[t] = ex[t] / s;
    }
    int base = blockIdx.x * GRU_NPB;
    for (int i = tid; i < GRU_NPB * (FSTRIDE / 2); i += GRU_NPB) {
        int nd = i / (FSTRIDE / 2), c2 = i - nd * (FSTRIDE / 2);
        int g = base + nd;
        float2 f = make_float2(0.f, 0.f);
        if (g < n) {
            unsigned u = __ldg((const unsigned*)(P + (size_t)g * FSTRIDE) + c2);
            f = __half22float2(bits_h2u(u));
        }
        sP[nd * 81 + 2 * c2]     = f.x;
        sP[nd * 81 + 2 * c2 + 1] = f.y;
    }
    __syncthreads();

    int node = base + tid;
    if (node >= n) return;
    const float* myP = &sP[tid * 81];

    float H[16], Hacc[16];
#pragma unroll
    for (int h = 0; h < 16; h++) { H[h] = 0.f; Hacc[h] = 0.f; }

#pragma unroll 1
    for (int t = 0; t < TT; t++) {
        unsigned long long pk2[16], hk2[16];
#pragma unroll
        for (int k = 0; k < 16; k++) {
            float pk = myP[t * 16 + k];
            pk2[k] = pack2(pk, pk);
            hk2[k] = pack2(H[k], H[k]);
        }

        unsigned long long acc[8];
        float a[16];
        // Z gate
#pragma unroll
        for (int j = 0; j < 8; j++) acc[j] = sB2z[j];
#pragma unroll
        for (int k = 0; k < 16; k++) {
#pragma unroll
            for (int j = 0; j < 8; j++) {
                acc[j] = fma2(pk2[k], sM2z[k * 8 + j], acc[j]);
                acc[j] = fma2(hk2[k], sL2z[k * 8 + j], acc[j]);
            }
        }
        float Zg[16];
#pragma unroll
        for (int j = 0; j < 8; j++) unpack2(a[2 * j], a[2 * j + 1], acc[j]);
#pragma unroll
        for (int h = 0; h < 16; h++) Zg[h] = fast_sig(a[h]);

        // R gate
#pragma unroll
        for (int j = 0; j < 8; j++) acc[j] = sB2r[j];
#pragma unroll
        for (int k = 0; k < 16; k++) {
#pragma unroll
            for (int j = 0; j < 8; j++) {
                acc[j] = fma2(pk2[k], sM2r[k * 8 + j], acc[j]);
                acc[j] = fma2(hk2[k], sL2r[k * 8 + j], acc[j]);
            }
        }
        float Rg[16];
#pragma unroll
        for (int j = 0; j < 8; j++) unpack2(a[2 * j], a[2 * j + 1], acc[j]);
#pragma unroll
        for (int h = 0; h < 16; h++) Rg[h] = fast_sig(a[h]);

        // candidate gate: uses H*Rg
#pragma unroll
        for (int k = 0; k < 16; k++) {
            float hr = H[k] * Rg[k];
            hk2[k] = pack2(hr, hr);
        }
#pragma unroll
        for (int j = 0; j < 8; j++) acc[j] = sB2h[j];
#pragma unroll
        for (int k = 0; k < 16; k++) {
#pragma unroll
            for (int j = 0; j < 8; j++) {
                acc[j] = fma2(pk2[k], sM2h[k * 8 + j], acc[j]);
                acc[j] = fma2(hk2[k], sL2h[k * 8 + j], acc[j]);
            }
        }
#pragma unroll
        for (int j = 0; j < 8; j++) unpack2(a[2 * j], a[2 * j + 1], acc[j]);
#pragma unroll
        for (int h = 0; h < 16; h++) {
            float ht = fast_tanh(a[h]);
            H[h] = Zg[h] * H[h] + (1.f - Zg[h]) * ht;
            Hacc[h] = fmaf(sprob[t], H[h], Hacc[h]);
        }
    }

    float l0 = sfcb[0], l1 = sfcb[1];
#pragma unroll
    for (int h = 0; h < 16; h++) {
        l0 = fmaf(Hacc[h], sfcW[h * 2 + 0], l0);
        l1 = fmaf(Hacc[h], sfcW[h * 2 + 1], l1);
    }
    float m = fmaxf(l0, l1);
    float lse = m + logf(expf(l0 - m) + expf(l1 - m));
    out[(size_t)node * 2 + 0] = l0 - lse;
    out[(size_t)node * 2 + 1] = l1 - lse;
}

// ---------------- launch ----------------
extern "C" void kernel_launch(void* const* d_in, const int* in_sizes, int n_in,
                              void* d_out, int out_size) {
    const float* x   = (const float*)d_in[0];
    const int*   src = (const int*)d_in[1];
    const int*   dst = (const int*)d_in[2];
    const float* W1  = (const float*)d_in[3];
    const float* b1  = (const float*)d_in[4];
    const float* W2  = (const float*)d_in[5];
    const float* b2  = (const float*)d_in[6];
    const float* Wz  = (const float*)d_in[7];
    const float* bz  = (const float*)d_in[8];
    const float* Wr  = (const float*)d_in[9];
    const float* br  = (const float*)d_in[10];
    const float* Wh  = (const float*)d_in[11];
    const float* bh  = (const float*)d_in[12];
    const float* Lz  = (const float*)d_in[13];
    const float* lz  = (const float*)d_in[14];
    const float* Lr  = (const float*)d_in[15];
    const float* lr  = (const float*)d_in[16];
    const float* Lh  = (const float*)d_in[17];
    const float* lh  = (const float*)d_in[18];
    const float* att = (const float*)d_in[19];
    const float* fcW = (const float*)d_in[20];
    const float* fcb = (const float*)d_in[21];

    int n = in_sizes[0] / (TT * FIN);
    int e = in_sizes[1];

    void* p;
    cudaGetSymbolAddress(&p, g_cnt);     int*           cnt    = (int*)p;
    cudaGetSymbolAddress(&p, g_deg);     int*           degv   = (int*)p;
    cudaGetSymbolAddress(&p, g_row);     int*           rowp   = (int*)p;
    cudaGetSymbolAddress(&p, g_cursor);  int*           cursor = (int*)p;
    cudaGetSymbolAddress(&p, g_dis);     float*         dis    = (float*)p;
    cudaGetSymbolAddress(&p, g_csrc);    int*           csrc   = (int*)p;
    cudaGetSymbolAddress(&p, g_xT);      __half*        xT     = (__half*)p;
    cudaGetSymbolAddress(&p, g_h1);      unsigned char* h1     = (unsigned char*)p;
    cudaGetSymbolAddress(&p, g_feats);   unsigned char* feats  = (unsigned char*)p;
    cudaGetSymbolAddress(&p, g_P);       __half*        P      = (__half*)p;

    int nb256_n = (n + 255) / 256;
    int nb256_e = (e + 255) / 256;
    int fill_threads = (e > n * XREAL) ? e : n * XREAL;
    int prop_blocks = (n + 7) / 8;

    // 0: degree count
    kcount<<<nb256_e, 256>>>(dst, cnt, e);
    // 1: offsets + dis
    koffsets<<<nb256_n, 256>>>(cnt, n);
    // 2: fused edge fill (src only) + x transpose pre-scaled by dis
    kfill2<<<(fill_threads + 255) / 256, 256>>>(src, dst, cursor, csrc, x, xT, dis, n, e);
    // 3: h1(fp8) = K8*dis*relu((S x) @ W1 + b1)   <-- profiled slot
    kprop_x<<<prop_blocks, 256>>>(xT, h1, rowp, degv, csrc, dis, W1, b1, n);
    // 4: feats(fp8) = K8*dis*relu((S h1) @ W2 + b2)
    kprop8<1><<<prop_blocks, 256>>>(h1, feats, rowp, degv, csrc, dis, W2, b2, n);
    // 5: P(fp16) = S feats
    kprop8<0><<<prop_blocks, 256>>>(feats, P, rowp, degv, csrc, dis, W2, b2, n);
    // 6: fold GRU gate weights
    kprepG<<<1, 256>>>(Wz, bz, Wr, br, Wh, bh, Lz, lz, Lr, lr, Lh, lh);
    // 7: GRU (FFMA2) + attention + FC + log_softmax
    kgru<<<(n + GRU_NPB - 1) / GRU_NPB, GRU_NPB>>>(P, Lz, Lr, Lh, att, fcW, fcb,
                                                   (float*)d_out, n);
}